// round 12
// baseline (speedup 1.0000x reference)
#include <cuda_runtime.h>
#include <math.h>
#include <stdint.h>

// Problem constants
#define Nn   4096
#define KK   8
#define FD   512
#define NFW  532          // 512 + 4 + 16
#define EAW  1029         // 5 + 2*512
#define NKE  (Nn*KK)      // 32768

// Output layout (flattened float32 concat of the tuple)
#define NF_OFF   ((size_t)0)
#define EI_OFF   ((size_t)Nn*NFW)                 // 2179072
#define EA_OFF   (EI_OFF + (size_t)2*NKE)         // 2244608 (EA_OFF % 4 == 0)
#define OCC_OFF  (EA_OFF + (size_t)NKE*EAW)       // 35962880
#define MASK_OFF (OCC_OFF + (size_t)Nn)           // 35966976

#define DIST_T   108.0f
#define DIST_T2  11666.0f
#define SENT_D   1e30f
#define SENT_I   0x7fffffff

// Spatial bins: 120-px cells, 16 x 9 grid
#define GX 16
#define GY 9
#define CELLS (GX*GY)
#define INV_CELL (1.0f/120.0f)

__device__ float2 g_c    [Nn];
__device__ int    g_start[CELLS+1];
__device__ float4 g_bc4  [Nn];       // binned: (cx, cy, idx-bits, 0)
__device__ float2 g_em   [NKE];      // (mask, dst-bits)
__device__ float  g_head [NKE*5];    // pre-masked per-edge scalars
__device__ int    g_flag = 0;        // bin-done flag (reset by k_edge)

// ===========================================================================
// MEGA kernel: block 0 = binning; blocks 1..512 = reid norm;
//              blocks 513..1024 = KNN (spin-wait on bin flag).
// ===========================================================================
__global__ void __launch_bounds__(256)
k_mega(const float* __restrict__ reid, const float* __restrict__ pos,
       float* __restrict__ out)
{
    __shared__ short srank[Nn];          // 8 KB (bin only)
    __shared__ int   scnt [CELLS];
    __shared__ int   sscan[256];
    __shared__ int   sst  [CELLS+1];

    int tid = threadIdx.x;
    int bid = blockIdx.x;
    int warp = tid >> 5, lane = tid & 31;

    if (bid == 0) {
        // ------------------- BINNING (count + scan + scatter) -------------
        if (tid < CELLS) scnt[tid] = 0;
        __syncthreads();

#pragma unroll
        for (int ii = 0; ii < 16; ii++) {
            int i = tid + 256*ii;
            float4 p = ((const float4*)pos)[i];
            float cx = 0.5f*(p.x+p.z), cy = 0.5f*(p.y+p.w);
            g_c[i] = make_float2(cx, cy);
            int bx = min((int)(cx * INV_CELL), GX-1);
            int by = min((int)(cy * INV_CELL), GY-1);
            srank[i] = (short)atomicAdd(&scnt[by*GX + bx], 1);
        }
        __syncthreads();

        // Hillis-Steele inclusive scan over 256 slots
        sscan[tid] = (tid < CELLS) ? scnt[tid] : 0;
        __syncthreads();
#pragma unroll
        for (int o = 1; o < 256; o <<= 1) {
            int x = (tid >= o) ? sscan[tid-o] : 0;
            __syncthreads();
            sscan[tid] += x;
            __syncthreads();
        }
        if (tid < CELLS) { sst[tid+1] = sscan[tid]; g_start[tid+1] = sscan[tid]; }
        if (tid == 0)    { sst[0] = 0;              g_start[0] = 0; }
        __syncthreads();

#pragma unroll
        for (int ii = 0; ii < 16; ii++) {
            int i = tid + 256*ii;
            float2 c = g_c[i];
            int bx = min((int)(c.x * INV_CELL), GX-1);
            int by = min((int)(c.y * INV_CELL), GY-1);
            int p = sst[by*GX + bx] + (int)srank[i];
            g_bc4[p] = make_float4(c.x, c.y, __int_as_float(i), 0.0f);
        }
        __syncthreads();
        __threadfence();
        if (tid == 0) atomicExch(&g_flag, 1);
        return;
    }

    if (bid <= 512) {
        // ------------------- REID NORM + pos_normed -----------------------
        int i = (bid - 1) * 8 + warp;

        const float4* r = (const float4*)(reid + (size_t)i * FD);
        float4 v[4];
        float s = 0.0f;
#pragma unroll
        for (int u = 0; u < 4; u++) {
            v[u] = r[lane + 32*u];
            s += v[u].x*v[u].x + v[u].y*v[u].y + v[u].z*v[u].z + v[u].w*v[u].w;
        }
#pragma unroll
        for (int o = 16; o > 0; o >>= 1) s += __shfl_xor_sync(0xffffffffu, s, o);
        float inv = 1.0f / (sqrtf(s) + 1e-12f);

        float4* o4 = (float4*)(out + (size_t)i * NFW);
#pragma unroll
        for (int u = 0; u < 4; u++) {
            float4 w = v[u];
            w.x *= inv; w.y *= inv; w.z *= inv; w.w *= inv;
            o4[lane + 32*u] = w;
        }

        if (lane == 0) {
            float4 p = ((const float4*)pos)[i];
            float cx = 0.5f*(p.x+p.z), cy = 0.5f*(p.y+p.w);
            float w = p.z - p.x, h = p.w - p.y;
            float* o = out + (size_t)i * NFW;
            o[512] = cx / 1920.0f;
            o[513] = cy / 1080.0f;
            o[514] = w  / 1920.0f;
            o[515] = h  / 1080.0f;
        }
        return;
    }

    // ----------------------- KNN (wait for binning) -----------------------
    if (tid == 0) {
        while (atomicAdd(&g_flag, 0) == 0) { __nanosleep(64); }
    }
    __syncthreads();
    __threadfence();

    if (tid < CELLS+1) sst[tid] = g_start[tid];
    __syncthreads();

    int i = (bid - 513) * 8 + warp;
    float2 ci = g_c[i];
    int bx = min((int)(ci.x * INV_CELL), GX-1);
    int by = min((int)(ci.y * INV_CELL), GY-1);

    float dist[KK]; int idx[KK];
#pragma unroll
    for (int u = 0; u < KK; u++) { dist[u] = SENT_D; idx[u] = SENT_I; }

    int y0 = max(by-1, 0), y1 = min(by+1, GY-1);
    int x0 = max(bx-1, 0), x1 = min(bx+1, GX-1);
    for (int cy2 = y0; cy2 <= y1; cy2++) {
        int st = sst[cy2*GX + x0], en = sst[cy2*GX + x1 + 1];
        for (int p = st + lane; p < en; p += 32) {
            float4 b = __ldg(&g_bc4[p]);
            int j = __float_as_int(b.z);
            float dx = ci.x - b.x;
            float dy = ci.y - b.y;
            float d2 = dx*dx + dy*dy;
            if (j != i && d2 <= DIST_T2) {
                float Dv = sqrtf(fmaxf(d2, 1e-12f));
                if (Dv <= DIST_T) {
                    float kd = Dv; int ki = j;
#pragma unroll
                    for (int u = 0; u < KK; u++) {
                        bool sw = (kd < dist[u]) || (kd == dist[u] && ki < idx[u]);
                        if (sw) {
                            float td = dist[u]; int ti = idx[u];
                            dist[u] = kd; idx[u] = ki;
                            kd = td; ki = ti;
                        }
                    }
                }
            }
        }
    }

    // warp merge: 8 rounds of packed (distBits, idx) min-reduce
    float res_d[KK]; int res_i[KK];
#pragma unroll
    for (int k = 0; k < KK; k++) {
        unsigned long long key =
            ((unsigned long long)__float_as_uint(dist[0]) << 32) | (unsigned)idx[0];
#pragma unroll
        for (int o = 16; o > 0; o >>= 1) {
            unsigned long long other = __shfl_xor_sync(0xffffffffu, key, o);
            if (other < key) key = other;
        }
        res_d[k] = __uint_as_float((unsigned)(key >> 32));
        res_i[k] = (int)(unsigned)(key & 0xffffffffull);
        unsigned long long mine =
            ((unsigned long long)__float_as_uint(dist[0]) << 32) | (unsigned)idx[0];
        if (mine == key) {
#pragma unroll
            for (int u = 0; u < KK-1; u++) { dist[u] = dist[u+1]; idx[u] = idx[u+1]; }
            dist[KK-1] = SENT_D; idx[KK-1] = SENT_I;
        }
    }
    // res_* now warp-uniform

    // ---- lanes 0..7: per-edge scalar stash ----
    if (lane < KK) {
        float d = SENT_D; int di = 0;
#pragma unroll
        for (int j = 0; j < KK; j++)
            if (lane == j) { d = res_d[j]; di = res_i[j]; }
        bool val = d < 1e9f;
        int dst = val ? di : 0;
        float m = val ? 1.0f : 0.0f;
        int e = i*KK + lane;

        float4 pi = ((const float4*)pos)[i];
        float4 pd = ((const float4*)pos)[dst];
        float cxi = 0.5f*(pi.x+pi.z), cyi = 0.5f*(pi.y+pi.w);
        float cxd = 0.5f*(pd.x+pd.z), cyd = 0.5f*(pd.y+pd.w);
        float wi = pi.z-pi.x, hi = pi.w-pi.y;
        float wd = pd.z-pd.x, hd = pd.w-pd.y;

        float xd = (cxi - cxd) / 1920.0f;
        float yd = (cyi - cyd) / 1080.0f;
        float ix1 = fmaxf(pi.x, pd.x), iy1 = fmaxf(pi.y, pd.y);
        float ix2 = fminf(pi.z, pd.z), iy2 = fminf(pi.w, pd.w);
        float inter = fmaxf(ix2-ix1, 0.0f) * fmaxf(iy2-iy1, 0.0f);
        float iou = inter / (wi*hi + wd*hd - inter + 1e-12f);
        float lw = logf(wi / wd);
        float lh = logf(hi / hd);

        g_head[e*5+0] = xd  * m;
        g_head[e*5+1] = yd  * m;
        g_head[e*5+2] = iou * m;
        g_head[e*5+3] = lw  * m;
        g_head[e*5+4] = lh  * m;
        g_em[e] = make_float2(m, __int_as_float(dst));

        out[EI_OFF + e]       = (float)i;
        out[EI_OFF + NKE + e] = (float)dst;
        out[MASK_OFF + e]     = m;

        if (lane == 0) {
            float occf = 0.0f;
            if (val) occf = (inter > wi*hi*0.5f) ? 1.0f : 0.0f;
            out[OCC_OFF + i] = occf;
        }
    }

    // ---- lane 0: topology features (nb_dist, angles) ----
    if (lane == 0) {
        bool val[KK]; float nd[KK], vx[KK], vy[KK];
#pragma unroll
        for (int k = 0; k < KK; k++) {
            val[k] = res_d[k] < 1e9f;
            nd[k]  = val[k] ? res_d[k] : 0.0f;
            int nik = val[k] ? res_i[k] : 0;
            float2 cn = g_c[nik];
            vx[k] = cn.x - ci.x;
            vy[k] = cn.y - ci.y;
        }
        float* nf = out + (size_t)i * NFW;
#pragma unroll
        for (int k = 0; k < KK; k++) nf[516 + k] = nd[k] / 1080.0f;

        const float LO = (float)(-1.0 + 1e-6);
        const float HI = (float)( 1.0 - 1e-6);
#pragma unroll
        for (int k = 0; k < KK-1; k++) {
            float a = 0.0f;
            if (val[k+1]) {
                float dot = vx[k]*vx[k+1] + vy[k]*vy[k+1];
                float n1 = sqrtf(vx[k]*vx[k] + vy[k]*vy[k]);
                float n2 = sqrtf(vx[k+1]*vx[k+1] + vy[k+1]*vy[k+1]);
                float cs = dot / (n1*n2 + 1e-12f);
                cs = fminf(fmaxf(cs, LO), HI);
                a = acosf(cs) * 57.29577951308232f;
            }
            nf[524 + k] = a / 360.0f;
        }
        nf[531] = 0.0f;
    }
}

// ===========================================================================
// K_EDGE: bulk reid copy + head scalars. TWO warps per edge.
//         Aligned float4 loads, shuffle-rotate, aligned float4 stores.
// ===========================================================================
__global__ void __launch_bounds__(256)
k_edge(float* __restrict__ out)
{
    if (blockIdx.x == 0 && threadIdx.x == 0) g_flag = 0;  // reset for replay

    const unsigned FULL = 0xffffffffu;
    int wp = threadIdx.x >> 5, lane = threadIdx.x & 31;
    int e = blockIdx.x * 4 + (wp >> 1);
    int half = wp & 1;                   // 0 = src half, 1 = dst half
    int i = e >> 3;

    float2 md = g_em[e];
    float m  = md.x;
    int  dst = __float_as_int(md.y);

    const float* nf = out;
    size_t B = EA_OFF + (size_t)e * EAW;
    int r = (e + 1) & 3;                 // (B+5) mod 4
    int a = (4 - r) & 3;                 // leading scalar count
    float4* ea4 = (float4*)(out + B + 5 + a);

    if (half == 0) {
        const float4* rs4 = (const float4*)(nf + (size_t)i * NFW);
        float4 v[4];
#pragma unroll
        for (int u = 0; u < 4; u++) v[u] = __ldg(rs4 + lane + 32*u);

        if (a == 0) {
#pragma unroll
            for (int u = 0; u < 4; u++) {
                float4 f = v[u];
                f.x *= m; f.y *= m; f.z *= m; f.w *= m;
                __stcs(ea4 + lane + 32*u, f);
            }
        } else {
            float4 e4 = __ldg((const float4*)(nf + (size_t)dst * NFW)); // dst quad 0
#pragma unroll
            for (int u = 0; u < 4; u++) {
                float4 f = v[u];
                float4 n;
                n.x = __shfl_sync(FULL, v[u].x, lane + 1);
                n.y = __shfl_sync(FULL, v[u].y, lane + 1);
                n.z = __shfl_sync(FULL, v[u].z, lane + 1);
                n.w = __shfl_sync(FULL, v[u].w, lane + 1);
                float4 f0;
                if (u < 3) {
                    f0.x = __shfl_sync(FULL, v[(u+1)&3].x, 0);
                    f0.y = __shfl_sync(FULL, v[(u+1)&3].y, 0);
                    f0.z = __shfl_sync(FULL, v[(u+1)&3].z, 0);
                    f0.w = __shfl_sync(FULL, v[(u+1)&3].w, 0);
                } else {
                    f0 = e4;
                }
                if (lane == 31) n = f0;

                float4 o;
                if      (a == 1) o = make_float4(f.y, f.z, f.w, n.x);
                else if (a == 2) o = make_float4(f.z, f.w, n.x, n.y);
                else             o = make_float4(f.w, n.x, n.y, n.z);
                o.x *= m; o.y *= m; o.z *= m; o.w *= m;
                __stcs(ea4 + lane + 32*u, o);
            }
        }
        // head: cols 0..4 <- g_head; cols 5..5+a-1 <- src[0..a)
        if (lane < 5)
            __stcs(out + B + lane, g_head[e*5 + lane]);
        else if (lane < 5 + a)
            __stcs(out + B + lane, __ldg(nf + (size_t)i * NFW + (lane - 5)) * m);
    } else {
        const float4* rd4 = (const float4*)(nf + (size_t)dst * NFW);
        float4 v[4];
#pragma unroll
        for (int u = 0; u < 4; u++) v[u] = __ldg(rd4 + lane + 32*u);

        if (a == 0) {
#pragma unroll
            for (int u = 0; u < 4; u++) {
                float4 f = v[u];
                f.x *= m; f.y *= m; f.z *= m; f.w *= m;
                __stcs(ea4 + lane + 32*(u+4), f);
            }
        } else {
#pragma unroll
            for (int u = 0; u < 4; u++) {
                float4 f = v[u];
                float4 n;
                n.x = __shfl_sync(FULL, v[u].x, lane + 1);
                n.y = __shfl_sync(FULL, v[u].y, lane + 1);
                n.z = __shfl_sync(FULL, v[u].z, lane + 1);
                n.w = __shfl_sync(FULL, v[u].w, lane + 1);
                float4 f0;
                f0.x = __shfl_sync(FULL, v[(u+1)&3].x, 0);
                f0.y = __shfl_sync(FULL, v[(u+1)&3].y, 0);
                f0.z = __shfl_sync(FULL, v[(u+1)&3].z, 0);
                f0.w = __shfl_sync(FULL, v[(u+1)&3].w, 0);
                if (lane == 31) n = f0;

                float4 o;
                if      (a == 1) o = make_float4(f.y, f.z, f.w, n.x);
                else if (a == 2) o = make_float4(f.z, f.w, n.x, n.y);
                else             o = make_float4(f.w, n.x, n.y, n.z);

                int q = lane + 32*(u+4);
                if (q < 255) {
                    o.x *= m; o.y *= m; o.z *= m; o.w *= m;
                    __stcs(ea4 + q, o);
                }
            }
            // tail: cols 1025+a..1028 <- dst[508+a..512)
            int t = 4 - a;
            if (lane < t)
                __stcs(out + B + 1025 + a + lane,
                       __ldg(nf + (size_t)dst * NFW + 508 + a + lane) * m);
        }
    }
}

// ---------------------------------------------------------------------------
extern "C" void kernel_launch(void* const* d_in, const int* in_sizes, int n_in,
                              void* d_out, int out_size)
{
    const float* reid = (const float*)d_in[0];
    const float* pos  = (const float*)d_in[1];
    float* out = (float*)d_out;

    k_mega<<<1025, 256>>>(reid, pos, out);
    k_edge<<<NKE/4, 256>>>(out);
}

// round 13
// speedup vs baseline: 1.4948x; 1.4948x over previous
#include <cuda_runtime.h>
#include <math.h>
#include <stdint.h>

// Problem constants
#define Nn   4096
#define KK   8
#define FD   512
#define NFW  532          // 512 + 4 + 16
#define EAW  1029         // 5 + 2*512
#define NKE  (Nn*KK)      // 32768

// Output layout (flattened float32 concat of the tuple)
#define NF_OFF   ((size_t)0)
#define EI_OFF   ((size_t)Nn*NFW)                 // 2179072
#define EA_OFF   (EI_OFF + (size_t)2*NKE)         // 2244608 (EA_OFF % 4 == 0)
#define OCC_OFF  (EA_OFF + (size_t)NKE*EAW)       // 35962880
#define MASK_OFF (OCC_OFF + (size_t)Nn)           // 35966976

#define DIST_T   108.0f
#define DIST_T2  11666.0f
#define SENT_D   1e30f
#define SENT_I   0x7fffffff

// Spatial bins: 120-px cells, 16 x 9 grid
#define GX 16
#define GY 9
#define CELLS (GX*GY)
#define INV_CELL (1.0f/120.0f)

__device__ float2 g_em  [NKE];       // (mask, dst-bits)
__device__ float  g_head[NKE*5];     // pre-masked per-edge scalars

// ===========================================================================
// MEGA v3: NO cross-block dependency.
//   blocks 0..511   : KNN — each block bins ALL 4096 points into its own
//                     smem (order-invariant selection), then scans 3x3 ring.
//   blocks 512..1023: reid norm + pos_normed.
// ===========================================================================
__global__ void __launch_bounds__(256)
k_mega(const float* __restrict__ reid, const float* __restrict__ pos,
       float* __restrict__ out)
{
    int tid = threadIdx.x;
    int bid = blockIdx.x;
    int warp = tid >> 5, lane = tid & 31;

    if (bid >= 512) {
        // ------------------- REID NORM + pos_normed -----------------------
        int i = (bid - 512) * 8 + warp;

        const float4* r = (const float4*)(reid + (size_t)i * FD);
        float4 v[4];
        float s = 0.0f;
#pragma unroll
        for (int u = 0; u < 4; u++) {
            v[u] = r[lane + 32*u];
            s += v[u].x*v[u].x + v[u].y*v[u].y + v[u].z*v[u].z + v[u].w*v[u].w;
        }
#pragma unroll
        for (int o = 16; o > 0; o >>= 1) s += __shfl_xor_sync(0xffffffffu, s, o);
        float inv = 1.0f / (sqrtf(s) + 1e-12f);

        float4* o4 = (float4*)(out + (size_t)i * NFW);
#pragma unroll
        for (int u = 0; u < 4; u++) {
            float4 w = v[u];
            w.x *= inv; w.y *= inv; w.z *= inv; w.w *= inv;
            o4[lane + 32*u] = w;
        }

        if (lane == 0) {
            float4 p = ((const float4*)pos)[i];
            float cx = 0.5f*(p.x+p.z), cy = 0.5f*(p.y+p.w);
            float w = p.z - p.x, h = p.w - p.y;
            float* o = out + (size_t)i * NFW;
            o[512] = cx / 1920.0f;
            o[513] = cy / 1080.0f;
            o[514] = w  / 1920.0f;
            o[515] = h  / 1080.0f;
        }
        return;
    }

    // =================== KNN block: local binning in smem ==================
    __shared__ float2         sxy [Nn];       // 32 KB binned centers
    __shared__ unsigned short sidx[Nn];       // 8 KB binned node ids
    __shared__ int            scnt[CELLS];
    __shared__ int            sscan[256];
    __shared__ int            sst [CELLS+1];

    if (tid < CELLS) scnt[tid] = 0;
    __syncthreads();

    // pass 1: count; remember (cell, rank) per handled node
    int cr[16];                                // packed: cell<<16 | rank
#pragma unroll
    for (int ii = 0; ii < 16; ii++) {
        int i = tid + 256*ii;
        float4 p = ((const float4*)pos)[i];
        float cx = 0.5f*(p.x+p.z), cy = 0.5f*(p.y+p.w);
        int bx = min((int)(cx * INV_CELL), GX-1);
        int by = min((int)(cy * INV_CELL), GY-1);
        int cell = by*GX + bx;
        int rank = atomicAdd(&scnt[cell], 1);
        cr[ii] = (cell << 16) | rank;
    }
    __syncthreads();

    // exclusive scan over 144 cells (Hillis-Steele on 256 slots)
    sscan[tid] = (tid < CELLS) ? scnt[tid] : 0;
    __syncthreads();
#pragma unroll
    for (int o = 1; o < 256; o <<= 1) {
        int x = (tid >= o) ? sscan[tid-o] : 0;
        __syncthreads();
        sscan[tid] += x;
        __syncthreads();
    }
    if (tid < CELLS) sst[tid+1] = sscan[tid];
    if (tid == 0)    sst[0] = 0;
    __syncthreads();

    // pass 2: scatter (reload pos from L2; it is resident)
#pragma unroll
    for (int ii = 0; ii < 16; ii++) {
        int i = tid + 256*ii;
        float4 p = ((const float4*)pos)[i];
        float cx = 0.5f*(p.x+p.z), cy = 0.5f*(p.y+p.w);
        int cell = cr[ii] >> 16;
        int rank = cr[ii] & 0xffff;
        int q = sst[cell] + rank;
        sxy [q] = make_float2(cx, cy);
        sidx[q] = (unsigned short)i;
    }
    __syncthreads();

    // ---------------- per-warp KNN over 3x3 cell ring ----------------
    int i = bid * 8 + warp;
    float4 pi4 = ((const float4*)pos)[i];
    float2 ci = make_float2(0.5f*(pi4.x+pi4.z), 0.5f*(pi4.y+pi4.w));
    int bx = min((int)(ci.x * INV_CELL), GX-1);
    int by = min((int)(ci.y * INV_CELL), GY-1);

    float dist[KK]; int idx[KK];
#pragma unroll
    for (int u = 0; u < KK; u++) { dist[u] = SENT_D; idx[u] = SENT_I; }

    int y0 = max(by-1, 0), y1 = min(by+1, GY-1);
    int x0 = max(bx-1, 0), x1 = min(bx+1, GX-1);
    for (int cy2 = y0; cy2 <= y1; cy2++) {
        int st = sst[cy2*GX + x0], en = sst[cy2*GX + x1 + 1];
        for (int p = st + lane; p < en; p += 32) {
            float2 b = sxy[p];
            int j = (int)sidx[p];
            float dx = ci.x - b.x;
            float dy = ci.y - b.y;
            float d2 = dx*dx + dy*dy;
            if (j != i && d2 <= DIST_T2) {
                float Dv = sqrtf(fmaxf(d2, 1e-12f));
                if (Dv <= DIST_T) {
                    float kd = Dv; int ki = j;
#pragma unroll
                    for (int u = 0; u < KK; u++) {
                        bool sw = (kd < dist[u]) || (kd == dist[u] && ki < idx[u]);
                        if (sw) {
                            float td = dist[u]; int ti = idx[u];
                            dist[u] = kd; idx[u] = ki;
                            kd = td; ki = ti;
                        }
                    }
                }
            }
        }
    }

    // warp merge: 8 rounds of packed (distBits, idx) min-reduce
    float res_d[KK]; int res_i[KK];
#pragma unroll
    for (int k = 0; k < KK; k++) {
        unsigned long long key =
            ((unsigned long long)__float_as_uint(dist[0]) << 32) | (unsigned)idx[0];
#pragma unroll
        for (int o = 16; o > 0; o >>= 1) {
            unsigned long long other = __shfl_xor_sync(0xffffffffu, key, o);
            if (other < key) key = other;
        }
        res_d[k] = __uint_as_float((unsigned)(key >> 32));
        res_i[k] = (int)(unsigned)(key & 0xffffffffull);
        unsigned long long mine =
            ((unsigned long long)__float_as_uint(dist[0]) << 32) | (unsigned)idx[0];
        if (mine == key) {
#pragma unroll
            for (int u = 0; u < KK-1; u++) { dist[u] = dist[u+1]; idx[u] = idx[u+1]; }
            dist[KK-1] = SENT_D; idx[KK-1] = SENT_I;
        }
    }
    // res_* now warp-uniform

    // ---- lanes 0..7: per-edge scalar stash ----
    if (lane < KK) {
        float d = SENT_D; int di = 0;
#pragma unroll
        for (int j = 0; j < KK; j++)
            if (lane == j) { d = res_d[j]; di = res_i[j]; }
        bool val = d < 1e9f;
        int dst = val ? di : 0;
        float m = val ? 1.0f : 0.0f;
        int e = i*KK + lane;

        float4 pi = pi4;
        float4 pd = ((const float4*)pos)[dst];
        float cxi = ci.x, cyi = ci.y;
        float cxd = 0.5f*(pd.x+pd.z), cyd = 0.5f*(pd.y+pd.w);
        float wi = pi.z-pi.x, hi = pi.w-pi.y;
        float wd = pd.z-pd.x, hd = pd.w-pd.y;

        float xd = (cxi - cxd) / 1920.0f;
        float yd = (cyi - cyd) / 1080.0f;
        float ix1 = fmaxf(pi.x, pd.x), iy1 = fmaxf(pi.y, pd.y);
        float ix2 = fminf(pi.z, pd.z), iy2 = fminf(pi.w, pd.w);
        float inter = fmaxf(ix2-ix1, 0.0f) * fmaxf(iy2-iy1, 0.0f);
        float iou = inter / (wi*hi + wd*hd - inter + 1e-12f);
        float lw = logf(wi / wd);
        float lh = logf(hi / hd);

        g_head[e*5+0] = xd  * m;
        g_head[e*5+1] = yd  * m;
        g_head[e*5+2] = iou * m;
        g_head[e*5+3] = lw  * m;
        g_head[e*5+4] = lh  * m;
        g_em[e] = make_float2(m, __int_as_float(dst));

        out[EI_OFF + e]       = (float)i;
        out[EI_OFF + NKE + e] = (float)dst;
        out[MASK_OFF + e]     = m;

        if (lane == 0) {
            float occf = 0.0f;
            if (val) occf = (inter > wi*hi*0.5f) ? 1.0f : 0.0f;
            out[OCC_OFF + i] = occf;
        }
    }

    // ---- lane 0: topology features (nb_dist, angles) ----
    if (lane == 0) {
        bool val[KK]; float nd[KK], vx[KK], vy[KK];
#pragma unroll
        for (int k = 0; k < KK; k++) {
            val[k] = res_d[k] < 1e9f;
            nd[k]  = val[k] ? res_d[k] : 0.0f;
            int nik = val[k] ? res_i[k] : 0;
            float4 pn = ((const float4*)pos)[nik];
            vx[k] = 0.5f*(pn.x+pn.z) - ci.x;
            vy[k] = 0.5f*(pn.y+pn.w) - ci.y;
        }
        float* nf = out + (size_t)i * NFW;
#pragma unroll
        for (int k = 0; k < KK; k++) nf[516 + k] = nd[k] / 1080.0f;

        const float LO = (float)(-1.0 + 1e-6);
        const float HI = (float)( 1.0 - 1e-6);
#pragma unroll
        for (int k = 0; k < KK-1; k++) {
            float a = 0.0f;
            if (val[k+1]) {
                float dot = vx[k]*vx[k+1] + vy[k]*vy[k+1];
                float n1 = sqrtf(vx[k]*vx[k] + vy[k]*vy[k]);
                float n2 = sqrtf(vx[k+1]*vx[k+1] + vy[k+1]*vy[k+1]);
                float cs = dot / (n1*n2 + 1e-12f);
                cs = fminf(fmaxf(cs, LO), HI);
                a = acosf(cs) * 57.29577951308232f;
            }
            nf[524 + k] = a / 360.0f;
        }
        nf[531] = 0.0f;
    }
}

// ===========================================================================
// K_EDGE (unchanged, proven): TWO warps per edge.
//         Aligned float4 loads, shuffle-rotate, aligned float4 stores.
// ===========================================================================
__global__ void __launch_bounds__(256)
k_edge(float* __restrict__ out)
{
    const unsigned FULL = 0xffffffffu;
    int wp = threadIdx.x >> 5, lane = threadIdx.x & 31;
    int e = blockIdx.x * 4 + (wp >> 1);
    int half = wp & 1;                   // 0 = src half, 1 = dst half
    int i = e >> 3;

    float2 md = g_em[e];
    float m  = md.x;
    int  dst = __float_as_int(md.y);

    const float* nf = out;
    size_t B = EA_OFF + (size_t)e * EAW;
    int r = (e + 1) & 3;                 // (B+5) mod 4
    int a = (4 - r) & 3;                 // leading scalar count
    float4* ea4 = (float4*)(out + B + 5 + a);

    if (half == 0) {
        const float4* rs4 = (const float4*)(nf + (size_t)i * NFW);
        float4 v[4];
#pragma unroll
        for (int u = 0; u < 4; u++) v[u] = __ldg(rs4 + lane + 32*u);

        if (a == 0) {
#pragma unroll
            for (int u = 0; u < 4; u++) {
                float4 f = v[u];
                f.x *= m; f.y *= m; f.z *= m; f.w *= m;
                __stcs(ea4 + lane + 32*u, f);
            }
        } else {
            float4 e4 = __ldg((const float4*)(nf + (size_t)dst * NFW)); // dst quad 0
#pragma unroll
            for (int u = 0; u < 4; u++) {
                float4 f = v[u];
                float4 n;
                n.x = __shfl_sync(FULL, v[u].x, lane + 1);
                n.y = __shfl_sync(FULL, v[u].y, lane + 1);
                n.z = __shfl_sync(FULL, v[u].z, lane + 1);
                n.w = __shfl_sync(FULL, v[u].w, lane + 1);
                float4 f0;
                if (u < 3) {
                    f0.x = __shfl_sync(FULL, v[(u+1)&3].x, 0);
                    f0.y = __shfl_sync(FULL, v[(u+1)&3].y, 0);
                    f0.z = __shfl_sync(FULL, v[(u+1)&3].z, 0);
                    f0.w = __shfl_sync(FULL, v[(u+1)&3].w, 0);
                } else {
                    f0 = e4;
                }
                if (lane == 31) n = f0;

                float4 o;
                if      (a == 1) o = make_float4(f.y, f.z, f.w, n.x);
                else if (a == 2) o = make_float4(f.z, f.w, n.x, n.y);
                else             o = make_float4(f.w, n.x, n.y, n.z);
                o.x *= m; o.y *= m; o.z *= m; o.w *= m;
                __stcs(ea4 + lane + 32*u, o);
            }
        }
        // head: cols 0..4 <- g_head; cols 5..5+a-1 <- src[0..a)
        if (lane < 5)
            __stcs(out + B + lane, g_head[e*5 + lane]);
        else if (lane < 5 + a)
            __stcs(out + B + lane, __ldg(nf + (size_t)i * NFW + (lane - 5)) * m);
    } else {
        const float4* rd4 = (const float4*)(nf + (size_t)dst * NFW);
        float4 v[4];
#pragma unroll
        for (int u = 0; u < 4; u++) v[u] = __ldg(rd4 + lane + 32*u);

        if (a == 0) {
#pragma unroll
            for (int u = 0; u < 4; u++) {
                float4 f = v[u];
                f.x *= m; f.y *= m; f.z *= m; f.w *= m;
                __stcs(ea4 + lane + 32*(u+4), f);
            }
        } else {
#pragma unroll
            for (int u = 0; u < 4; u++) {
                float4 f = v[u];
                float4 n;
                n.x = __shfl_sync(FULL, v[u].x, lane + 1);
                n.y = __shfl_sync(FULL, v[u].y, lane + 1);
                n.z = __shfl_sync(FULL, v[u].z, lane + 1);
                n.w = __shfl_sync(FULL, v[u].w, lane + 1);
                float4 f0;
                f0.x = __shfl_sync(FULL, v[(u+1)&3].x, 0);
                f0.y = __shfl_sync(FULL, v[(u+1)&3].y, 0);
                f0.z = __shfl_sync(FULL, v[(u+1)&3].z, 0);
                f0.w = __shfl_sync(FULL, v[(u+1)&3].w, 0);
                if (lane == 31) n = f0;

                float4 o;
                if      (a == 1) o = make_float4(f.y, f.z, f.w, n.x);
                else if (a == 2) o = make_float4(f.z, f.w, n.x, n.y);
                else             o = make_float4(f.w, n.x, n.y, n.z);

                int q = lane + 32*(u+4);
                if (q < 255) {
                    o.x *= m; o.y *= m; o.z *= m; o.w *= m;
                    __stcs(ea4 + q, o);
                }
            }
            // tail: cols 1025+a..1028 <- dst[508+a..512)
            int t = 4 - a;
            if (lane < t)
                __stcs(out + B + 1025 + a + lane,
                       __ldg(nf + (size_t)dst * NFW + 508 + a + lane) * m);
        }
    }
}

// ---------------------------------------------------------------------------
extern "C" void kernel_launch(void* const* d_in, const int* in_sizes, int n_in,
                              void* d_out, int out_size)
{
    const float* reid = (const float*)d_in[0];
    const float* pos  = (const float*)d_in[1];
    float* out = (float*)d_out;

    k_mega<<<1024, 256>>>(reid, pos, out);
    k_edge<<<NKE/4, 256>>>(out);
}

// round 14
// speedup vs baseline: 1.5163x; 1.0144x over previous
#include <cuda_runtime.h>
#include <math.h>
#include <stdint.h>

// Problem constants
#define Nn   4096
#define KK   8
#define FD   512
#define NFW  532          // 512 + 4 + 16
#define EAW  1029         // 5 + 2*512
#define NKE  (Nn*KK)      // 32768

// Output layout (flattened float32 concat of the tuple)
#define NF_OFF   ((size_t)0)
#define EI_OFF   ((size_t)Nn*NFW)                 // 2179072
#define EA_OFF   (EI_OFF + (size_t)2*NKE)         // 2244608 (EA_OFF % 4 == 0)
#define OCC_OFF  (EA_OFF + (size_t)NKE*EAW)       // 35962880
#define MASK_OFF (OCC_OFF + (size_t)Nn)           // 35966976

#define DIST_T   108.0f
#define DIST_T2  11666.0f
#define SENT_D   1e30f
#define SENT_I   0x7fffffff

// Spatial bins: 120-px cells, 16 x 9 grid
#define GX 16
#define GY 9
#define CELLS (GX*GY)
#define INV_CELL (1.0f/120.0f)

__device__ float  g_inv  [Nn];       // 1/(||reid_i|| + eps)
__device__ float2 g_c    [Nn];
__device__ int    g_start[CELLS+1];
__device__ float4 g_bc4  [Nn];       // binned: (cx, cy, idx-bits, 0)
__device__ float2 g_em   [NKE];      // (mask, dst-bits)
__device__ float  g_head [NKE*5];    // pre-masked per-edge scalars

// ===========================================================================
// K1: blocks 0..511 compute g_inv (one warp per row, read-only);
//     block 512 does binning (count + scan + scatter).
// ===========================================================================
__global__ void __launch_bounds__(256)
k_pre(const float* __restrict__ reid, const float* __restrict__ pos)
{
    __shared__ short srank[Nn];          // bin block only
    __shared__ int   scnt [CELLS];
    __shared__ int   sscan[256];
    __shared__ int   sst  [CELLS+1];

    int tid = threadIdx.x;
    int bid = blockIdx.x;
    int warp = tid >> 5, lane = tid & 31;

    if (bid < 512) {
        // ---- inv-norm: 8 warps x 1 row ----
        int i = bid * 8 + warp;
        const float4* r = (const float4*)(reid + (size_t)i * FD);
        float s = 0.0f;
#pragma unroll
        for (int u = 0; u < 4; u++) {
            float4 v = r[lane + 32*u];
            s += v.x*v.x + v.y*v.y + v.z*v.z + v.w*v.w;
        }
#pragma unroll
        for (int o = 16; o > 0; o >>= 1) s += __shfl_xor_sync(0xffffffffu, s, o);
        if (lane == 0) g_inv[i] = 1.0f / (sqrtf(s) + 1e-12f);
        return;
    }

    // ---- binning ----
    if (tid < CELLS) scnt[tid] = 0;
    __syncthreads();

#pragma unroll
    for (int ii = 0; ii < 16; ii++) {
        int i = tid + 256*ii;
        float4 p = ((const float4*)pos)[i];
        float cx = 0.5f*(p.x+p.z), cy = 0.5f*(p.y+p.w);
        g_c[i] = make_float2(cx, cy);
        int bx = min((int)(cx * INV_CELL), GX-1);
        int by = min((int)(cy * INV_CELL), GY-1);
        srank[i] = (short)atomicAdd(&scnt[by*GX + bx], 1);
    }
    __syncthreads();

    sscan[tid] = (tid < CELLS) ? scnt[tid] : 0;
    __syncthreads();
#pragma unroll
    for (int o = 1; o < 256; o <<= 1) {
        int x = (tid >= o) ? sscan[tid-o] : 0;
        __syncthreads();
        sscan[tid] += x;
        __syncthreads();
    }
    if (tid < CELLS) { sst[tid+1] = sscan[tid]; g_start[tid+1] = sscan[tid]; }
    if (tid == 0)    { sst[0] = 0;              g_start[0] = 0; }
    __syncthreads();

#pragma unroll
    for (int ii = 0; ii < 16; ii++) {
        int i = tid + 256*ii;
        float2 c = g_c[i];
        int bx = min((int)(c.x * INV_CELL), GX-1);
        int by = min((int)(c.y * INV_CELL), GY-1);
        int p = sst[by*GX + bx] + (int)srank[i];
        g_bc4[p] = make_float4(c.x, c.y, __int_as_float(i), 0.0f);
    }
}

// ===========================================================================
// K2: KNN over 3x3 cell ring (one warp per node) + topology + occ +
//     edge scalar stash + edge_index + mask. (proven R8 code)
// ===========================================================================
__global__ void __launch_bounds__(256)
k_knn(const float* __restrict__ pos, float* __restrict__ out)
{
    __shared__ int sst[CELLS+1];
    int tid = threadIdx.x;
    if (tid < CELLS+1) sst[tid] = g_start[tid];
    __syncthreads();

    int warp = tid >> 5, lane = tid & 31;
    int i = blockIdx.x * 8 + warp;
    float2 ci = g_c[i];
    int bx = min((int)(ci.x * INV_CELL), GX-1);
    int by = min((int)(ci.y * INV_CELL), GY-1);

    float dist[KK]; int idx[KK];
#pragma unroll
    for (int u = 0; u < KK; u++) { dist[u] = SENT_D; idx[u] = SENT_I; }

    int y0 = max(by-1, 0), y1 = min(by+1, GY-1);
    int x0 = max(bx-1, 0), x1 = min(bx+1, GX-1);
    for (int cy2 = y0; cy2 <= y1; cy2++) {
        int st = sst[cy2*GX + x0], en = sst[cy2*GX + x1 + 1];
        for (int p = st + lane; p < en; p += 32) {
            float4 b = __ldg(&g_bc4[p]);
            int j = __float_as_int(b.z);
            float dx = ci.x - b.x;
            float dy = ci.y - b.y;
            float d2 = dx*dx + dy*dy;
            if (j != i && d2 <= DIST_T2) {
                float Dv = sqrtf(fmaxf(d2, 1e-12f));
                if (Dv <= DIST_T) {
                    float kd = Dv; int ki = j;
#pragma unroll
                    for (int u = 0; u < KK; u++) {
                        bool sw = (kd < dist[u]) || (kd == dist[u] && ki < idx[u]);
                        if (sw) {
                            float td = dist[u]; int ti = idx[u];
                            dist[u] = kd; idx[u] = ki;
                            kd = td; ki = ti;
                        }
                    }
                }
            }
        }
    }

    // warp merge: 8 rounds of packed (distBits, idx) min-reduce
    float res_d[KK]; int res_i[KK];
#pragma unroll
    for (int k = 0; k < KK; k++) {
        unsigned long long key =
            ((unsigned long long)__float_as_uint(dist[0]) << 32) | (unsigned)idx[0];
#pragma unroll
        for (int o = 16; o > 0; o >>= 1) {
            unsigned long long other = __shfl_xor_sync(0xffffffffu, key, o);
            if (other < key) key = other;
        }
        res_d[k] = __uint_as_float((unsigned)(key >> 32));
        res_i[k] = (int)(unsigned)(key & 0xffffffffull);
        unsigned long long mine =
            ((unsigned long long)__float_as_uint(dist[0]) << 32) | (unsigned)idx[0];
        if (mine == key) {
#pragma unroll
            for (int u = 0; u < KK-1; u++) { dist[u] = dist[u+1]; idx[u] = idx[u+1]; }
            dist[KK-1] = SENT_D; idx[KK-1] = SENT_I;
        }
    }
    // res_* now warp-uniform

    // ---- lanes 0..7: per-edge scalar stash ----
    if (lane < KK) {
        float d = SENT_D; int di = 0;
#pragma unroll
        for (int j = 0; j < KK; j++)
            if (lane == j) { d = res_d[j]; di = res_i[j]; }
        bool val = d < 1e9f;
        int dst = val ? di : 0;
        float m = val ? 1.0f : 0.0f;
        int e = i*KK + lane;

        float4 pi = ((const float4*)pos)[i];
        float4 pd = ((const float4*)pos)[dst];
        float cxi = 0.5f*(pi.x+pi.z), cyi = 0.5f*(pi.y+pi.w);
        float cxd = 0.5f*(pd.x+pd.z), cyd = 0.5f*(pd.y+pd.w);
        float wi = pi.z-pi.x, hi = pi.w-pi.y;
        float wd = pd.z-pd.x, hd = pd.w-pd.y;

        float xd = (cxi - cxd) / 1920.0f;
        float yd = (cyi - cyd) / 1080.0f;
        float ix1 = fmaxf(pi.x, pd.x), iy1 = fmaxf(pi.y, pd.y);
        float ix2 = fminf(pi.z, pd.z), iy2 = fminf(pi.w, pd.w);
        float inter = fmaxf(ix2-ix1, 0.0f) * fmaxf(iy2-iy1, 0.0f);
        float iou = inter / (wi*hi + wd*hd - inter + 1e-12f);
        float lw = logf(wi / wd);
        float lh = logf(hi / hd);

        g_head[e*5+0] = xd  * m;
        g_head[e*5+1] = yd  * m;
        g_head[e*5+2] = iou * m;
        g_head[e*5+3] = lw  * m;
        g_head[e*5+4] = lh  * m;
        g_em[e] = make_float2(m, __int_as_float(dst));

        out[EI_OFF + e]       = (float)i;
        out[EI_OFF + NKE + e] = (float)dst;
        out[MASK_OFF + e]     = m;

        if (lane == 0) {
            float occf = 0.0f;
            if (val) occf = (inter > wi*hi*0.5f) ? 1.0f : 0.0f;
            out[OCC_OFF + i] = occf;
        }
    }

    // ---- lane 0: topology features (nb_dist, angles) ----
    if (lane == 0) {
        bool val[KK]; float nd[KK], vx[KK], vy[KK];
#pragma unroll
        for (int k = 0; k < KK; k++) {
            val[k] = res_d[k] < 1e9f;
            nd[k]  = val[k] ? res_d[k] : 0.0f;
            int nik = val[k] ? res_i[k] : 0;
            float2 cn = g_c[nik];
            vx[k] = cn.x - ci.x;
            vy[k] = cn.y - ci.y;
        }
        float* nf = out + (size_t)i * NFW;
#pragma unroll
        for (int k = 0; k < KK; k++) nf[516 + k] = nd[k] / 1080.0f;

        const float LO = (float)(-1.0 + 1e-6);
        const float HI = (float)( 1.0 - 1e-6);
#pragma unroll
        for (int k = 0; k < KK-1; k++) {
            float a = 0.0f;
            if (val[k+1]) {
                float dot = vx[k]*vx[k+1] + vy[k]*vy[k+1];
                float n1 = sqrtf(vx[k]*vx[k] + vy[k]*vy[k]);
                float n2 = sqrtf(vx[k+1]*vx[k+1] + vy[k+1]*vy[k+1]);
                float cs = dot / (n1*n2 + 1e-12f);
                cs = fminf(fmaxf(cs, LO), HI);
                a = acosf(cs) * 57.29577951308232f;
            }
            nf[524 + k] = a / 360.0f;
        }
        nf[531] = 0.0f;
    }
}

// ===========================================================================
// K3: edge copy (blocks 0..8191, sourcing raw reid * g_inv) +
//     node_feat norm-write (blocks 8192..8703).
// ===========================================================================
__global__ void __launch_bounds__(256)
k_edge(const float* __restrict__ reid, const float* __restrict__ pos,
       float* __restrict__ out)
{
    const unsigned FULL = 0xffffffffu;
    int wp = threadIdx.x >> 5, lane = threadIdx.x & 31;
    int bid = blockIdx.x;

    if (bid >= 8192) {
        // ---------------- node_feat write: reid*inv + pos_normed ----------
        int i = (bid - 8192) * 8 + wp;
        float inv = g_inv[i];
        const float4* r = (const float4*)(reid + (size_t)i * FD);
        float4* o4 = (float4*)(out + (size_t)i * NFW);
#pragma unroll
        for (int u = 0; u < 4; u++) {
            float4 v = r[lane + 32*u];
            v.x *= inv; v.y *= inv; v.z *= inv; v.w *= inv;
            o4[lane + 32*u] = v;
        }
        if (lane == 0) {
            float4 p = ((const float4*)pos)[i];
            float cx = 0.5f*(p.x+p.z), cy = 0.5f*(p.y+p.w);
            float w = p.z - p.x, h = p.w - p.y;
            float* o = out + (size_t)i * NFW;
            o[512] = cx / 1920.0f;
            o[513] = cy / 1080.0f;
            o[514] = w  / 1920.0f;
            o[515] = h  / 1080.0f;
        }
        return;
    }

    // ---------------- edge copy: two warps per edge --------------------
    int e = bid * 4 + (wp >> 1);
    int half = wp & 1;                   // 0 = src half, 1 = dst half
    int i = e >> 3;

    float2 md = g_em[e];
    float m  = md.x;
    int  dst = __float_as_int(md.y);

    size_t B = EA_OFF + (size_t)e * EAW;
    int r = (e + 1) & 3;                 // (B+5) mod 4
    int a = (4 - r) & 3;                 // leading scalar count
    float4* ea4 = (float4*)(out + B + 5 + a);

    if (half == 0) {
        float sc = g_inv[i] * m;         // exact: m in {0,1}
        const float4* rs4 = (const float4*)(reid + (size_t)i * FD);
        float4 v[4];
#pragma unroll
        for (int u = 0; u < 4; u++) v[u] = __ldg(rs4 + lane + 32*u);

        if (a == 0) {
#pragma unroll
            for (int u = 0; u < 4; u++) {
                float4 f = v[u];
                f.x *= sc; f.y *= sc; f.z *= sc; f.w *= sc;
                __stcs(ea4 + lane + 32*u, f);
            }
        } else {
            float scd = g_inv[dst] * m;
            float4 e4 = __ldg((const float4*)(reid + (size_t)dst * FD)); // dst quad 0
            e4.x *= scd; e4.y *= scd; e4.z *= scd; e4.w *= scd;
#pragma unroll
            for (int u = 0; u < 4; u++) {
                float4 f = v[u];
                f.x *= sc; f.y *= sc; f.z *= sc; f.w *= sc;
                float4 n;
                n.x = __shfl_sync(FULL, f.x, lane + 1);
                n.y = __shfl_sync(FULL, f.y, lane + 1);
                n.z = __shfl_sync(FULL, f.z, lane + 1);
                n.w = __shfl_sync(FULL, f.w, lane + 1);
                // lane31 needs first quad of next u (scaled); compute via shuffle
                float4 vn = v[(u+1)&3];
                float4 f0;
                f0.x = __shfl_sync(FULL, vn.x, 0) * sc;
                f0.y = __shfl_sync(FULL, vn.y, 0) * sc;
                f0.z = __shfl_sync(FULL, vn.z, 0) * sc;
                f0.w = __shfl_sync(FULL, vn.w, 0) * sc;
                if (u == 3) f0 = e4;
                if (lane == 31) n = f0;

                float4 o;
                if      (a == 1) o = make_float4(f.y, f.z, f.w, n.x);
                else if (a == 2) o = make_float4(f.z, f.w, n.x, n.y);
                else             o = make_float4(f.w, n.x, n.y, n.z);
                __stcs(ea4 + lane + 32*u, o);
            }
        }
        // head: cols 0..4 <- g_head; cols 5..5+a-1 <- src reid[0..a)*inv*m
        if (lane < 5)
            __stcs(out + B + lane, g_head[e*5 + lane]);
        else if (lane < 5 + a)
            __stcs(out + B + lane, __ldg(reid + (size_t)i * FD + (lane - 5)) * sc);
    } else {
        float sc = g_inv[dst] * m;
        const float4* rd4 = (const float4*)(reid + (size_t)dst * FD);
        float4 v[4];
#pragma unroll
        for (int u = 0; u < 4; u++) v[u] = __ldg(rd4 + lane + 32*u);

        if (a == 0) {
#pragma unroll
            for (int u = 0; u < 4; u++) {
                float4 f = v[u];
                f.x *= sc; f.y *= sc; f.z *= sc; f.w *= sc;
                __stcs(ea4 + lane + 32*(u+4), f);
            }
        } else {
#pragma unroll
            for (int u = 0; u < 4; u++) {
                float4 f = v[u];
                f.x *= sc; f.y *= sc; f.z *= sc; f.w *= sc;
                float4 n;
                n.x = __shfl_sync(FULL, f.x, lane + 1);
                n.y = __shfl_sync(FULL, f.y, lane + 1);
                n.z = __shfl_sync(FULL, f.z, lane + 1);
                n.w = __shfl_sync(FULL, f.w, lane + 1);
                float4 vn = v[(u+1)&3];
                float4 f0;
                f0.x = __shfl_sync(FULL, vn.x, 0) * sc;
                f0.y = __shfl_sync(FULL, vn.y, 0) * sc;
                f0.z = __shfl_sync(FULL, vn.z, 0) * sc;
                f0.w = __shfl_sync(FULL, vn.w, 0) * sc;
                if (lane == 31) n = f0;

                float4 o;
                if      (a == 1) o = make_float4(f.y, f.z, f.w, n.x);
                else if (a == 2) o = make_float4(f.z, f.w, n.x, n.y);
                else             o = make_float4(f.w, n.x, n.y, n.z);

                int q = lane + 32*(u+4);
                if (q < 255) __stcs(ea4 + q, o);
            }
            // tail: cols 1025+a..1028 <- dst reid[508+a..512)*inv*m
            int t = 4 - a;
            if (lane < t)
                __stcs(out + B + 1025 + a + lane,
                       __ldg(reid + (size_t)dst * FD + 508 + a + lane) * sc);
        }
    }
}

// ---------------------------------------------------------------------------
extern "C" void kernel_launch(void* const* d_in, const int* in_sizes, int n_in,
                              void* d_out, int out_size)
{
    const float* reid = (const float*)d_in[0];
    const float* pos  = (const float*)d_in[1];
    float* out = (float*)d_out;

    k_pre <<<513, 256>>>(reid, pos);
    k_knn <<<Nn/8, 256>>>(pos, out);
    k_edge<<<8704, 256>>>(reid, pos, out);
}

// round 15
// speedup vs baseline: 1.5508x; 1.0227x over previous
#include <cuda_runtime.h>
#include <math.h>
#include <stdint.h>

// Problem constants
#define Nn   4096
#define KK   8
#define FD   512
#define NFW  532          // 512 + 4 + 16
#define EAW  1029         // 5 + 2*512
#define NKE  (Nn*KK)      // 32768

// Output layout (flattened float32 concat of the tuple)
#define NF_OFF   ((size_t)0)
#define EI_OFF   ((size_t)Nn*NFW)                 // 2179072
#define EA_OFF   (EI_OFF + (size_t)2*NKE)         // 2244608 (EA_OFF % 4 == 0)
#define OCC_OFF  (EA_OFF + (size_t)NKE*EAW)       // 35962880
#define MASK_OFF (OCC_OFF + (size_t)Nn)           // 35966976

#define DIST_T   108.0f
#define DIST_T2  11666.0f
#define SENT_D   1e30f
#define SENT_I   0x7fffffff

// Spatial bins: 120-px cells, 16 x 9 grid
#define GX 16
#define GY 9
#define CELLS (GX*GY)
#define INV_CELL (1.0f/120.0f)

__device__ float  g_inv  [Nn];       // 1/(||reid_i|| + eps)
__device__ float2 g_c    [Nn];
__device__ int    g_start[CELLS+1];
__device__ float4 g_bc4  [Nn];       // binned: (cx, cy, idx-bits, 0)
__device__ float2 g_em   [NKE];      // (mask, dst-bits)
__device__ float  g_head [NKE*5];    // pre-masked per-edge scalars

// ===========================================================================
// K1 (1024-thread blocks): blocks 0..127 compute g_inv (32 warps x 1 row);
//     block 128 does binning with 1024 threads (count + scan + scatter).
// ===========================================================================
__global__ void __launch_bounds__(1024)
k_pre(const float* __restrict__ reid, const float* __restrict__ pos)
{
    __shared__ short srank[Nn];          // bin block only (8 KB)
    __shared__ int   scnt [CELLS];
    __shared__ int   sscan[256];
    __shared__ int   sst  [CELLS+1];

    int tid = threadIdx.x;
    int bid = blockIdx.x;
    int warp = tid >> 5, lane = tid & 31;

    if (bid < 128) {
        // ---- inv-norm: 32 warps x 1 row ----
        int i = bid * 32 + warp;
        const float4* r = (const float4*)(reid + (size_t)i * FD);
        float s = 0.0f;
#pragma unroll
        for (int u = 0; u < 4; u++) {
            float4 v = r[lane + 32*u];
            s += v.x*v.x + v.y*v.y + v.z*v.z + v.w*v.w;
        }
#pragma unroll
        for (int o = 16; o > 0; o >>= 1) s += __shfl_xor_sync(0xffffffffu, s, o);
        if (lane == 0) g_inv[i] = 1.0f / (sqrtf(s) + 1e-12f);
        return;
    }

    // ---- binning (1024 threads) ----
    if (tid < CELLS) scnt[tid] = 0;
    __syncthreads();

#pragma unroll
    for (int ii = 0; ii < 4; ii++) {
        int i = tid + 1024*ii;
        float4 p = ((const float4*)pos)[i];
        float cx = 0.5f*(p.x+p.z), cy = 0.5f*(p.y+p.w);
        g_c[i] = make_float2(cx, cy);
        int bx = min((int)(cx * INV_CELL), GX-1);
        int by = min((int)(cy * INV_CELL), GY-1);
        srank[i] = (short)atomicAdd(&scnt[by*GX + bx], 1);
    }
    __syncthreads();

    // Hillis-Steele inclusive scan over 256 slots
    if (tid < 256) sscan[tid] = (tid < CELLS) ? scnt[tid] : 0;
    __syncthreads();
#pragma unroll
    for (int o = 1; o < 256; o <<= 1) {
        int x = (tid < 256 && tid >= o) ? sscan[tid-o] : 0;
        __syncthreads();
        if (tid < 256) sscan[tid] += x;
        __syncthreads();
    }
    if (tid < CELLS) { sst[tid+1] = sscan[tid]; g_start[tid+1] = sscan[tid]; }
    if (tid == 0)    { sst[0] = 0;              g_start[0] = 0; }
    __syncthreads();

#pragma unroll
    for (int ii = 0; ii < 4; ii++) {
        int i = tid + 1024*ii;
        float2 c = g_c[i];
        int bx = min((int)(c.x * INV_CELL), GX-1);
        int by = min((int)(c.y * INV_CELL), GY-1);
        int p = sst[by*GX + bx] + (int)srank[i];
        g_bc4[p] = make_float4(c.x, c.y, __int_as_float(i), 0.0f);
    }
}

// ===========================================================================
// K2: KNN over 3x3 cell ring (one warp per node) + topology + occ +
//     edge scalar stash + edge_index + mask. (proven R8 code)
// ===========================================================================
__global__ void __launch_bounds__(256)
k_knn(const float* __restrict__ pos, float* __restrict__ out)
{
    __shared__ int sst[CELLS+1];
    int tid = threadIdx.x;
    if (tid < CELLS+1) sst[tid] = g_start[tid];
    __syncthreads();

    int warp = tid >> 5, lane = tid & 31;
    int i = blockIdx.x * 8 + warp;
    float2 ci = g_c[i];
    int bx = min((int)(ci.x * INV_CELL), GX-1);
    int by = min((int)(ci.y * INV_CELL), GY-1);

    float dist[KK]; int idx[KK];
#pragma unroll
    for (int u = 0; u < KK; u++) { dist[u] = SENT_D; idx[u] = SENT_I; }

    int y0 = max(by-1, 0), y1 = min(by+1, GY-1);
    int x0 = max(bx-1, 0), x1 = min(bx+1, GX-1);
    for (int cy2 = y0; cy2 <= y1; cy2++) {
        int st = sst[cy2*GX + x0], en = sst[cy2*GX + x1 + 1];
        for (int p = st + lane; p < en; p += 32) {
            float4 b = __ldg(&g_bc4[p]);
            int j = __float_as_int(b.z);
            float dx = ci.x - b.x;
            float dy = ci.y - b.y;
            float d2 = dx*dx + dy*dy;
            if (j != i && d2 <= DIST_T2) {
                float Dv = sqrtf(fmaxf(d2, 1e-12f));
                if (Dv <= DIST_T) {
                    float kd = Dv; int ki = j;
#pragma unroll
                    for (int u = 0; u < KK; u++) {
                        bool sw = (kd < dist[u]) || (kd == dist[u] && ki < idx[u]);
                        if (sw) {
                            float td = dist[u]; int ti = idx[u];
                            dist[u] = kd; idx[u] = ki;
                            kd = td; ki = ti;
                        }
                    }
                }
            }
        }
    }

    // warp merge: 8 rounds of packed (distBits, idx) min-reduce
    float res_d[KK]; int res_i[KK];
#pragma unroll
    for (int k = 0; k < KK; k++) {
        unsigned long long key =
            ((unsigned long long)__float_as_uint(dist[0]) << 32) | (unsigned)idx[0];
#pragma unroll
        for (int o = 16; o > 0; o >>= 1) {
            unsigned long long other = __shfl_xor_sync(0xffffffffu, key, o);
            if (other < key) key = other;
        }
        res_d[k] = __uint_as_float((unsigned)(key >> 32));
        res_i[k] = (int)(unsigned)(key & 0xffffffffull);
        unsigned long long mine =
            ((unsigned long long)__float_as_uint(dist[0]) << 32) | (unsigned)idx[0];
        if (mine == key) {
#pragma unroll
            for (int u = 0; u < KK-1; u++) { dist[u] = dist[u+1]; idx[u] = idx[u+1]; }
            dist[KK-1] = SENT_D; idx[KK-1] = SENT_I;
        }
    }
    // res_* now warp-uniform

    // ---- lanes 0..7: per-edge scalar stash ----
    if (lane < KK) {
        float d = SENT_D; int di = 0;
#pragma unroll
        for (int j = 0; j < KK; j++)
            if (lane == j) { d = res_d[j]; di = res_i[j]; }
        bool val = d < 1e9f;
        int dst = val ? di : 0;
        float m = val ? 1.0f : 0.0f;
        int e = i*KK + lane;

        float4 pi = ((const float4*)pos)[i];
        float4 pd = ((const float4*)pos)[dst];
        float cxi = 0.5f*(pi.x+pi.z), cyi = 0.5f*(pi.y+pi.w);
        float cxd = 0.5f*(pd.x+pd.z), cyd = 0.5f*(pd.y+pd.w);
        float wi = pi.z-pi.x, hi = pi.w-pi.y;
        float wd = pd.z-pd.x, hd = pd.w-pd.y;

        float xd = (cxi - cxd) / 1920.0f;
        float yd = (cyi - cyd) / 1080.0f;
        float ix1 = fmaxf(pi.x, pd.x), iy1 = fmaxf(pi.y, pd.y);
        float ix2 = fminf(pi.z, pd.z), iy2 = fminf(pi.w, pd.w);
        float inter = fmaxf(ix2-ix1, 0.0f) * fmaxf(iy2-iy1, 0.0f);
        float iou = inter / (wi*hi + wd*hd - inter + 1e-12f);
        float lw = logf(wi / wd);
        float lh = logf(hi / hd);

        g_head[e*5+0] = xd  * m;
        g_head[e*5+1] = yd  * m;
        g_head[e*5+2] = iou * m;
        g_head[e*5+3] = lw  * m;
        g_head[e*5+4] = lh  * m;
        g_em[e] = make_float2(m, __int_as_float(dst));

        out[EI_OFF + e]       = (float)i;
        out[EI_OFF + NKE + e] = (float)dst;
        out[MASK_OFF + e]     = m;

        if (lane == 0) {
            float occf = 0.0f;
            if (val) occf = (inter > wi*hi*0.5f) ? 1.0f : 0.0f;
            out[OCC_OFF + i] = occf;
        }
    }

    // ---- lane 0: topology features (nb_dist, angles) ----
    if (lane == 0) {
        bool val[KK]; float nd[KK], vx[KK], vy[KK];
#pragma unroll
        for (int k = 0; k < KK; k++) {
            val[k] = res_d[k] < 1e9f;
            nd[k]  = val[k] ? res_d[k] : 0.0f;
            int nik = val[k] ? res_i[k] : 0;
            float2 cn = g_c[nik];
            vx[k] = cn.x - ci.x;
            vy[k] = cn.y - ci.y;
        }
        float* nf = out + (size_t)i * NFW;
#pragma unroll
        for (int k = 0; k < KK; k++) nf[516 + k] = nd[k] / 1080.0f;

        const float LO = (float)(-1.0 + 1e-6);
        const float HI = (float)( 1.0 - 1e-6);
#pragma unroll
        for (int k = 0; k < KK-1; k++) {
            float a = 0.0f;
            if (val[k+1]) {
                float dot = vx[k]*vx[k+1] + vy[k]*vy[k+1];
                float n1 = sqrtf(vx[k]*vx[k] + vy[k]*vy[k]);
                float n2 = sqrtf(vx[k+1]*vx[k+1] + vy[k+1]*vy[k+1]);
                float cs = dot / (n1*n2 + 1e-12f);
                cs = fminf(fmaxf(cs, LO), HI);
                a = acosf(cs) * 57.29577951308232f;
            }
            nf[524 + k] = a / 360.0f;
        }
        nf[531] = 0.0f;
    }
}

// ===========================================================================
// K3: edge copy (blocks 0..8191, sourcing raw reid * g_inv) +
//     node_feat norm-write (blocks 8192..8703). (unchanged from R14)
// ===========================================================================
__global__ void __launch_bounds__(256)
k_edge(const float* __restrict__ reid, const float* __restrict__ pos,
       float* __restrict__ out)
{
    const unsigned FULL = 0xffffffffu;
    int wp = threadIdx.x >> 5, lane = threadIdx.x & 31;
    int bid = blockIdx.x;

    if (bid >= 8192) {
        // ---------------- node_feat write: reid*inv + pos_normed ----------
        int i = (bid - 8192) * 8 + wp;
        float inv = g_inv[i];
        const float4* r = (const float4*)(reid + (size_t)i * FD);
        float4* o4 = (float4*)(out + (size_t)i * NFW);
#pragma unroll
        for (int u = 0; u < 4; u++) {
            float4 v = r[lane + 32*u];
            v.x *= inv; v.y *= inv; v.z *= inv; v.w *= inv;
            o4[lane + 32*u] = v;
        }
        if (lane == 0) {
            float4 p = ((const float4*)pos)[i];
            float cx = 0.5f*(p.x+p.z), cy = 0.5f*(p.y+p.w);
            float w = p.z - p.x, h = p.w - p.y;
            float* o = out + (size_t)i * NFW;
            o[512] = cx / 1920.0f;
            o[513] = cy / 1080.0f;
            o[514] = w  / 1920.0f;
            o[515] = h  / 1080.0f;
        }
        return;
    }

    // ---------------- edge copy: two warps per edge --------------------
    int e = bid * 4 + (wp >> 1);
    int half = wp & 1;                   // 0 = src half, 1 = dst half
    int i = e >> 3;

    float2 md = g_em[e];
    float m  = md.x;
    int  dst = __float_as_int(md.y);

    size_t B = EA_OFF + (size_t)e * EAW;
    int r = (e + 1) & 3;                 // (B+5) mod 4
    int a = (4 - r) & 3;                 // leading scalar count
    float4* ea4 = (float4*)(out + B + 5 + a);

    if (half == 0) {
        float sc = g_inv[i] * m;         // exact: m in {0,1}
        const float4* rs4 = (const float4*)(reid + (size_t)i * FD);
        float4 v[4];
#pragma unroll
        for (int u = 0; u < 4; u++) v[u] = __ldg(rs4 + lane + 32*u);

        if (a == 0) {
#pragma unroll
            for (int u = 0; u < 4; u++) {
                float4 f = v[u];
                f.x *= sc; f.y *= sc; f.z *= sc; f.w *= sc;
                __stcs(ea4 + lane + 32*u, f);
            }
        } else {
            float scd = g_inv[dst] * m;
            float4 e4 = __ldg((const float4*)(reid + (size_t)dst * FD)); // dst quad 0
            e4.x *= scd; e4.y *= scd; e4.z *= scd; e4.w *= scd;
#pragma unroll
            for (int u = 0; u < 4; u++) {
                float4 f = v[u];
                f.x *= sc; f.y *= sc; f.z *= sc; f.w *= sc;
                float4 n;
                n.x = __shfl_sync(FULL, f.x, lane + 1);
                n.y = __shfl_sync(FULL, f.y, lane + 1);
                n.z = __shfl_sync(FULL, f.z, lane + 1);
                n.w = __shfl_sync(FULL, f.w, lane + 1);
                float4 vn = v[(u+1)&3];
                float4 f0;
                f0.x = __shfl_sync(FULL, vn.x, 0) * sc;
                f0.y = __shfl_sync(FULL, vn.y, 0) * sc;
                f0.z = __shfl_sync(FULL, vn.z, 0) * sc;
                f0.w = __shfl_sync(FULL, vn.w, 0) * sc;
                if (u == 3) f0 = e4;
                if (lane == 31) n = f0;

                float4 o;
                if      (a == 1) o = make_float4(f.y, f.z, f.w, n.x);
                else if (a == 2) o = make_float4(f.z, f.w, n.x, n.y);
                else             o = make_float4(f.w, n.x, n.y, n.z);
                __stcs(ea4 + lane + 32*u, o);
            }
        }
        // head: cols 0..4 <- g_head; cols 5..5+a-1 <- src reid[0..a)*inv*m
        if (lane < 5)
            __stcs(out + B + lane, g_head[e*5 + lane]);
        else if (lane < 5 + a)
            __stcs(out + B + lane, __ldg(reid + (size_t)i * FD + (lane - 5)) * sc);
    } else {
        float sc = g_inv[dst] * m;
        const float4* rd4 = (const float4*)(reid + (size_t)dst * FD);
        float4 v[4];
#pragma unroll
        for (int u = 0; u < 4; u++) v[u] = __ldg(rd4 + lane + 32*u);

        if (a == 0) {
#pragma unroll
            for (int u = 0; u < 4; u++) {
                float4 f = v[u];
                f.x *= sc; f.y *= sc; f.z *= sc; f.w *= sc;
                __stcs(ea4 + lane + 32*(u+4), f);
            }
        } else {
#pragma unroll
            for (int u = 0; u < 4; u++) {
                float4 f = v[u];
                f.x *= sc; f.y *= sc; f.z *= sc; f.w *= sc;
                float4 n;
                n.x = __shfl_sync(FULL, f.x, lane + 1);
                n.y = __shfl_sync(FULL, f.y, lane + 1);
                n.z = __shfl_sync(FULL, f.z, lane + 1);
                n.w = __shfl_sync(FULL, f.w, lane + 1);
                float4 vn = v[(u+1)&3];
                float4 f0;
                f0.x = __shfl_sync(FULL, vn.x, 0) * sc;
                f0.y = __shfl_sync(FULL, vn.y, 0) * sc;
                f0.z = __shfl_sync(FULL, vn.z, 0) * sc;
                f0.w = __shfl_sync(FULL, vn.w, 0) * sc;
                if (lane == 31) n = f0;

                float4 o;
                if      (a == 1) o = make_float4(f.y, f.z, f.w, n.x);
                else if (a == 2) o = make_float4(f.z, f.w, n.x, n.y);
                else             o = make_float4(f.w, n.x, n.y, n.z);

                int q = lane + 32*(u+4);
                if (q < 255) __stcs(ea4 + q, o);
            }
            // tail: cols 1025+a..1028 <- dst reid[508+a..512)*inv*m
            int t = 4 - a;
            if (lane < t)
                __stcs(out + B + 1025 + a + lane,
                       __ldg(reid + (size_t)dst * FD + 508 + a + lane) * sc);
        }
    }
}

// ---------------------------------------------------------------------------
extern "C" void kernel_launch(void* const* d_in, const int* in_sizes, int n_in,
                              void* d_out, int out_size)
{
    const float* reid = (const float*)d_in[0];
    const float* pos  = (const float*)d_in[1];
    float* out = (float*)d_out;

    k_pre <<<129, 1024>>>(reid, pos);
    k_knn <<<Nn/8, 256>>>(pos, out);
    k_edge<<<8704, 256>>>(reid, pos, out);
}

// round 16
// speedup vs baseline: 1.5550x; 1.0027x over previous
#include <cuda_runtime.h>
#include <math.h>
#include <stdint.h>

// Problem constants
#define Nn   4096
#define KK   8
#define FD   512
#define NFW  532          // 512 + 4 + 16
#define EAW  1029         // 5 + 2*512
#define NKE  (Nn*KK)      // 32768

// Output layout (flattened float32 concat of the tuple)
#define NF_OFF   ((size_t)0)
#define EI_OFF   ((size_t)Nn*NFW)                 // 2179072
#define EA_OFF   (EI_OFF + (size_t)2*NKE)         // 2244608 (EA_OFF % 4 == 0)
#define OCC_OFF  (EA_OFF + (size_t)NKE*EAW)       // 35962880
#define MASK_OFF (OCC_OFF + (size_t)Nn)           // 35966976

#define DIST_T   108.0f
#define DIST_T2  11666.0f
#define SENT_D   1e30f
#define SENT_I   0x7fffffff

// Spatial bins: 120-px cells, 16 x 9 grid
#define GX 16
#define GY 9
#define CELLS (GX*GY)
#define INV_CELL (1.0f/120.0f)

__device__ float  g_inv  [Nn];       // 1/(||reid_i|| + eps)
__device__ float2 g_c    [Nn];
__device__ int    g_start[CELLS+1];
__device__ float4 g_bc4  [Nn];       // binned: (cx, cy, idx-bits, 0)
__device__ float2 g_em   [NKE];      // (mask, dst-bits)
__device__ float  g_head [NKE*5];    // pre-masked per-edge scalars
__device__ int    g_flag = 0;        // bin-done flag (reset by k_edge)

// ===========================================================================
// K1 (merged): 513 blocks x 256.
//   block 0      : binning (count + scan + scatter), then sets g_flag.
//   blocks 1..512: inv-norm for 8 rows (hides under binning), spin on flag,
//                  then KNN + topology + occ + edge scalar stash.
// ===========================================================================
__global__ void __launch_bounds__(256)
k_knn(const float* __restrict__ reid, const float* __restrict__ pos,
      float* __restrict__ out)
{
    __shared__ short srank[Nn];          // bin block only (8 KB)
    __shared__ int   scnt [CELLS];
    __shared__ int   sscan[256];
    __shared__ int   sst  [CELLS+1];     // bin: starts; knn: cached starts

    int tid = threadIdx.x;
    int bid = blockIdx.x;
    int warp = tid >> 5, lane = tid & 31;

    if (bid == 0) {
        // ------------------- BINNING (count + scan + scatter) -------------
        if (tid < CELLS) scnt[tid] = 0;
        __syncthreads();

#pragma unroll
        for (int ii = 0; ii < 16; ii++) {
            int i = tid + 256*ii;
            float4 p = ((const float4*)pos)[i];
            float cx = 0.5f*(p.x+p.z), cy = 0.5f*(p.y+p.w);
            g_c[i] = make_float2(cx, cy);
            int bx = min((int)(cx * INV_CELL), GX-1);
            int by = min((int)(cy * INV_CELL), GY-1);
            srank[i] = (short)atomicAdd(&scnt[by*GX + bx], 1);
        }
        __syncthreads();

        sscan[tid] = (tid < CELLS) ? scnt[tid] : 0;
        __syncthreads();
#pragma unroll
        for (int o = 1; o < 256; o <<= 1) {
            int x = (tid >= o) ? sscan[tid-o] : 0;
            __syncthreads();
            sscan[tid] += x;
            __syncthreads();
        }
        if (tid < CELLS) { sst[tid+1] = sscan[tid]; g_start[tid+1] = sscan[tid]; }
        if (tid == 0)    { sst[0] = 0;              g_start[0] = 0; }
        __syncthreads();

#pragma unroll
        for (int ii = 0; ii < 16; ii++) {
            int i = tid + 256*ii;
            float2 c = g_c[i];
            int bx = min((int)(c.x * INV_CELL), GX-1);
            int by = min((int)(c.y * INV_CELL), GY-1);
            int p = sst[by*GX + bx] + (int)srank[i];
            g_bc4[p] = make_float4(c.x, c.y, __int_as_float(i), 0.0f);
        }
        __syncthreads();
        __threadfence();
        if (tid == 0) atomicExch(&g_flag, 1);
        return;
    }

    int i = (bid - 1) * 8 + warp;        // this warp's node/row

    // ---- inv-norm (runs concurrently with binning; no dependency) ----
    {
        const float4* r = (const float4*)(reid + (size_t)i * FD);
        float s = 0.0f;
#pragma unroll
        for (int u = 0; u < 4; u++) {
            float4 v = r[lane + 32*u];
            s += v.x*v.x + v.y*v.y + v.z*v.z + v.w*v.w;
        }
#pragma unroll
        for (int o = 16; o > 0; o >>= 1) s += __shfl_xor_sync(0xffffffffu, s, o);
        if (lane == 0) g_inv[i] = 1.0f / (sqrtf(s) + 1e-12f);
    }

    // ---- wait for binning ----
    if (tid == 0) {
        while (atomicAdd(&g_flag, 0) == 0) { __nanosleep(64); }
    }
    __syncthreads();
    __threadfence();

    if (tid < CELLS+1) sst[tid] = g_start[tid];
    __syncthreads();

    // ---- KNN over 3x3 cell ring ----
    float2 ci = g_c[i];
    int bx = min((int)(ci.x * INV_CELL), GX-1);
    int by = min((int)(ci.y * INV_CELL), GY-1);

    float dist[KK]; int idx[KK];
#pragma unroll
    for (int u = 0; u < KK; u++) { dist[u] = SENT_D; idx[u] = SENT_I; }

    int y0 = max(by-1, 0), y1 = min(by+1, GY-1);
    int x0 = max(bx-1, 0), x1 = min(bx+1, GX-1);
    for (int cy2 = y0; cy2 <= y1; cy2++) {
        int st = sst[cy2*GX + x0], en = sst[cy2*GX + x1 + 1];
        for (int p = st + lane; p < en; p += 32) {
            float4 b = __ldg(&g_bc4[p]);
            int j = __float_as_int(b.z);
            float dx = ci.x - b.x;
            float dy = ci.y - b.y;
            float d2 = dx*dx + dy*dy;
            if (j != i && d2 <= DIST_T2) {
                float Dv = sqrtf(fmaxf(d2, 1e-12f));
                if (Dv <= DIST_T) {
                    float kd = Dv; int ki = j;
#pragma unroll
                    for (int u = 0; u < KK; u++) {
                        bool sw = (kd < dist[u]) || (kd == dist[u] && ki < idx[u]);
                        if (sw) {
                            float td = dist[u]; int ti = idx[u];
                            dist[u] = kd; idx[u] = ki;
                            kd = td; ki = ti;
                        }
                    }
                }
            }
        }
    }

    // warp merge: 8 rounds of packed (distBits, idx) min-reduce
    float res_d[KK]; int res_i[KK];
#pragma unroll
    for (int k = 0; k < KK; k++) {
        unsigned long long key =
            ((unsigned long long)__float_as_uint(dist[0]) << 32) | (unsigned)idx[0];
#pragma unroll
        for (int o = 16; o > 0; o >>= 1) {
            unsigned long long other = __shfl_xor_sync(0xffffffffu, key, o);
            if (other < key) key = other;
        }
        res_d[k] = __uint_as_float((unsigned)(key >> 32));
        res_i[k] = (int)(unsigned)(key & 0xffffffffull);
        unsigned long long mine =
            ((unsigned long long)__float_as_uint(dist[0]) << 32) | (unsigned)idx[0];
        if (mine == key) {
#pragma unroll
            for (int u = 0; u < KK-1; u++) { dist[u] = dist[u+1]; idx[u] = idx[u+1]; }
            dist[KK-1] = SENT_D; idx[KK-1] = SENT_I;
        }
    }
    // res_* now warp-uniform

    // ---- lanes 0..7: per-edge scalar stash ----
    if (lane < KK) {
        float d = SENT_D; int di = 0;
#pragma unroll
        for (int j = 0; j < KK; j++)
            if (lane == j) { d = res_d[j]; di = res_i[j]; }
        bool val = d < 1e9f;
        int dst = val ? di : 0;
        float m = val ? 1.0f : 0.0f;
        int e = i*KK + lane;

        float4 pi = ((const float4*)pos)[i];
        float4 pd = ((const float4*)pos)[dst];
        float cxi = 0.5f*(pi.x+pi.z), cyi = 0.5f*(pi.y+pi.w);
        float cxd = 0.5f*(pd.x+pd.z), cyd = 0.5f*(pd.y+pd.w);
        float wi = pi.z-pi.x, hi = pi.w-pi.y;
        float wd = pd.z-pd.x, hd = pd.w-pd.y;

        float xd = (cxi - cxd) / 1920.0f;
        float yd = (cyi - cyd) / 1080.0f;
        float ix1 = fmaxf(pi.x, pd.x), iy1 = fmaxf(pi.y, pd.y);
        float ix2 = fminf(pi.z, pd.z), iy2 = fminf(pi.w, pd.w);
        float inter = fmaxf(ix2-ix1, 0.0f) * fmaxf(iy2-iy1, 0.0f);
        float iou = inter / (wi*hi + wd*hd - inter + 1e-12f);
        float lw = logf(wi / wd);
        float lh = logf(hi / hd);

        g_head[e*5+0] = xd  * m;
        g_head[e*5+1] = yd  * m;
        g_head[e*5+2] = iou * m;
        g_head[e*5+3] = lw  * m;
        g_head[e*5+4] = lh  * m;
        g_em[e] = make_float2(m, __int_as_float(dst));

        out[EI_OFF + e]       = (float)i;
        out[EI_OFF + NKE + e] = (float)dst;
        out[MASK_OFF + e]     = m;

        if (lane == 0) {
            float occf = 0.0f;
            if (val) occf = (inter > wi*hi*0.5f) ? 1.0f : 0.0f;
            out[OCC_OFF + i] = occf;
        }
    }

    // ---- lane 0: topology features (nb_dist, angles) ----
    if (lane == 0) {
        bool val[KK]; float nd[KK], vx[KK], vy[KK];
#pragma unroll
        for (int k = 0; k < KK; k++) {
            val[k] = res_d[k] < 1e9f;
            nd[k]  = val[k] ? res_d[k] : 0.0f;
            int nik = val[k] ? res_i[k] : 0;
            float2 cn = g_c[nik];
            vx[k] = cn.x - ci.x;
            vy[k] = cn.y - ci.y;
        }
        float* nf = out + (size_t)i * NFW;
#pragma unroll
        for (int k = 0; k < KK; k++) nf[516 + k] = nd[k] / 1080.0f;

        const float LO = (float)(-1.0 + 1e-6);
        const float HI = (float)( 1.0 - 1e-6);
#pragma unroll
        for (int k = 0; k < KK-1; k++) {
            float a = 0.0f;
            if (val[k+1]) {
                float dot = vx[k]*vx[k+1] + vy[k]*vy[k+1];
                float n1 = sqrtf(vx[k]*vx[k] + vy[k]*vy[k]);
                float n2 = sqrtf(vx[k+1]*vx[k+1] + vy[k+1]*vy[k+1]);
                float cs = dot / (n1*n2 + 1e-12f);
                cs = fminf(fmaxf(cs, LO), HI);
                a = acosf(cs) * 57.29577951308232f;
            }
            nf[524 + k] = a / 360.0f;
        }
        nf[531] = 0.0f;
    }
}

// ===========================================================================
// K2: edge copy (blocks 0..8191, sourcing raw reid * g_inv) +
//     node_feat norm-write (blocks 8192..8703). (unchanged from R15,
//     plus g_flag reset for graph replay)
// ===========================================================================
__global__ void __launch_bounds__(256)
k_edge(const float* __restrict__ reid, const float* __restrict__ pos,
       float* __restrict__ out)
{
    if (blockIdx.x == 0 && threadIdx.x == 0) g_flag = 0;  // reset for replay

    const unsigned FULL = 0xffffffffu;
    int wp = threadIdx.x >> 5, lane = threadIdx.x & 31;
    int bid = blockIdx.x;

    if (bid >= 8192) {
        // ---------------- node_feat write: reid*inv + pos_normed ----------
        int i = (bid - 8192) * 8 + wp;
        float inv = g_inv[i];
        const float4* r = (const float4*)(reid + (size_t)i * FD);
        float4* o4 = (float4*)(out + (size_t)i * NFW);
#pragma unroll
        for (int u = 0; u < 4; u++) {
            float4 v = r[lane + 32*u];
            v.x *= inv; v.y *= inv; v.z *= inv; v.w *= inv;
            o4[lane + 32*u] = v;
        }
        if (lane == 0) {
            float4 p = ((const float4*)pos)[i];
            float cx = 0.5f*(p.x+p.z), cy = 0.5f*(p.y+p.w);
            float w = p.z - p.x, h = p.w - p.y;
            float* o = out + (size_t)i * NFW;
            o[512] = cx / 1920.0f;
            o[513] = cy / 1080.0f;
            o[514] = w  / 1920.0f;
            o[515] = h  / 1080.0f;
        }
        return;
    }

    // ---------------- edge copy: two warps per edge --------------------
    int e = bid * 4 + (wp >> 1);
    int half = wp & 1;                   // 0 = src half, 1 = dst half
    int i = e >> 3;

    float2 md = g_em[e];
    float m  = md.x;
    int  dst = __float_as_int(md.y);

    size_t B = EA_OFF + (size_t)e * EAW;
    int r = (e + 1) & 3;                 // (B+5) mod 4
    int a = (4 - r) & 3;                 // leading scalar count
    float4* ea4 = (float4*)(out + B + 5 + a);

    if (half == 0) {
        float sc = g_inv[i] * m;         // exact: m in {0,1}
        const float4* rs4 = (const float4*)(reid + (size_t)i * FD);
        float4 v[4];
#pragma unroll
        for (int u = 0; u < 4; u++) v[u] = __ldg(rs4 + lane + 32*u);

        if (a == 0) {
#pragma unroll
            for (int u = 0; u < 4; u++) {
                float4 f = v[u];
                f.x *= sc; f.y *= sc; f.z *= sc; f.w *= sc;
                __stcs(ea4 + lane + 32*u, f);
            }
        } else {
            float scd = g_inv[dst] * m;
            float4 e4 = __ldg((const float4*)(reid + (size_t)dst * FD)); // dst quad 0
            e4.x *= scd; e4.y *= scd; e4.z *= scd; e4.w *= scd;
#pragma unroll
            for (int u = 0; u < 4; u++) {
                float4 f = v[u];
                f.x *= sc; f.y *= sc; f.z *= sc; f.w *= sc;
                float4 n;
                n.x = __shfl_sync(FULL, f.x, lane + 1);
                n.y = __shfl_sync(FULL, f.y, lane + 1);
                n.z = __shfl_sync(FULL, f.z, lane + 1);
                n.w = __shfl_sync(FULL, f.w, lane + 1);
                float4 vn = v[(u+1)&3];
                float4 f0;
                f0.x = __shfl_sync(FULL, vn.x, 0) * sc;
                f0.y = __shfl_sync(FULL, vn.y, 0) * sc;
                f0.z = __shfl_sync(FULL, vn.z, 0) * sc;
                f0.w = __shfl_sync(FULL, vn.w, 0) * sc;
                if (u == 3) f0 = e4;
                if (lane == 31) n = f0;

                float4 o;
                if      (a == 1) o = make_float4(f.y, f.z, f.w, n.x);
                else if (a == 2) o = make_float4(f.z, f.w, n.x, n.y);
                else             o = make_float4(f.w, n.x, n.y, n.z);
                __stcs(ea4 + lane + 32*u, o);
            }
        }
        // head: cols 0..4 <- g_head; cols 5..5+a-1 <- src reid[0..a)*inv*m
        if (lane < 5)
            __stcs(out + B + lane, g_head[e*5 + lane]);
        else if (lane < 5 + a)
            __stcs(out + B + lane, __ldg(reid + (size_t)i * FD + (lane - 5)) * sc);
    } else {
        float sc = g_inv[dst] * m;
        const float4* rd4 = (const float4*)(reid + (size_t)dst * FD);
        float4 v[4];
#pragma unroll
        for (int u = 0; u < 4; u++) v[u] = __ldg(rd4 + lane + 32*u);

        if (a == 0) {
#pragma unroll
            for (int u = 0; u < 4; u++) {
                float4 f = v[u];
                f.x *= sc; f.y *= sc; f.z *= sc; f.w *= sc;
                __stcs(ea4 + lane + 32*(u+4), f);
            }
        } else {
#pragma unroll
            for (int u = 0; u < 4; u++) {
                float4 f = v[u];
                f.x *= sc; f.y *= sc; f.z *= sc; f.w *= sc;
                float4 n;
                n.x = __shfl_sync(FULL, f.x, lane + 1);
                n.y = __shfl_sync(FULL, f.y, lane + 1);
                n.z = __shfl_sync(FULL, f.z, lane + 1);
                n.w = __shfl_sync(FULL, f.w, lane + 1);
                float4 vn = v[(u+1)&3];
                float4 f0;
                f0.x = __shfl_sync(FULL, vn.x, 0) * sc;
                f0.y = __shfl_sync(FULL, vn.y, 0) * sc;
                f0.z = __shfl_sync(FULL, vn.z, 0) * sc;
                f0.w = __shfl_sync(FULL, vn.w, 0) * sc;
                if (lane == 31) n = f0;

                float4 o;
                if      (a == 1) o = make_float4(f.y, f.z, f.w, n.x);
                else if (a == 2) o = make_float4(f.z, f.w, n.x, n.y);
                else             o = make_float4(f.w, n.x, n.y, n.z);

                int q = lane + 32*(u+4);
                if (q < 255) __stcs(ea4 + q, o);
            }
            // tail: cols 1025+a..1028 <- dst reid[508+a..512)*inv*m
            int t = 4 - a;
            if (lane < t)
                __stcs(out + B + 1025 + a + lane,
                       __ldg(reid + (size_t)dst * FD + 508 + a + lane) * sc);
        }
    }
}

// ---------------------------------------------------------------------------
extern "C" void kernel_launch(void* const* d_in, const int* in_sizes, int n_in,
                              void* d_out, int out_size)
{
    const float* reid = (const float*)d_in[0];
    const float* pos  = (const float*)d_in[1];
    float* out = (float*)d_out;

    k_knn <<<513, 256>>>(reid, pos, out);
    k_edge<<<8704, 256>>>(reid, pos, out);
}

// round 17
// speedup vs baseline: 1.5633x; 1.0054x over previous
#include <cuda_runtime.h>
#include <math.h>
#include <stdint.h>

// Problem constants
#define Nn   4096
#define KK   8
#define FD   512
#define NFW  532          // 512 + 4 + 16
#define EAW  1029         // 5 + 2*512
#define NKE  (Nn*KK)      // 32768

// Output layout (flattened float32 concat of the tuple)
#define NF_OFF   ((size_t)0)
#define EI_OFF   ((size_t)Nn*NFW)                 // 2179072
#define EA_OFF   (EI_OFF + (size_t)2*NKE)         // 2244608 (EA_OFF % 4 == 0)
#define OCC_OFF  (EA_OFF + (size_t)NKE*EAW)       // 35962880
#define MASK_OFF (OCC_OFF + (size_t)Nn)           // 35966976

#define DIST_T   108.0f
#define DIST_T2  11666.0f
#define SENT_D   1e30f
#define SENT_I   0x7fffffff

// Spatial bins: 120-px cells, 16 x 9 grid
#define GX 16
#define GY 9
#define CELLS (GX*GY)
#define INV_CELL (1.0f/120.0f)

__device__ float  g_inv  [Nn];       // 1/(||reid_i|| + eps)
__device__ float2 g_c    [Nn];
__device__ int    g_start[CELLS+1];
__device__ float4 g_bc4  [Nn];       // binned: (cx, cy, idx-bits, 0)
__device__ float2 g_em   [NKE];      // (mask, dst-bits)
__device__ float  g_head [NKE*5];    // pre-masked per-edge scalars
__device__ int    g_flag = 0;        // bin-done flag (reset by k_edge)

// ===========================================================================
// K1 (merged): 513 blocks x 256.
//   block 0      : binning (count + scan + scatter), then sets g_flag.
//   blocks 1..512: FULL norm (read reid, reduce, write node_feat row +
//                  pos_normed + g_inv) — hides under binning — then spin
//                  on flag, then KNN + topology + occ + edge scalar stash.
// ===========================================================================
__global__ void __launch_bounds__(256)
k_knn(const float* __restrict__ reid, const float* __restrict__ pos,
      float* __restrict__ out)
{
    __shared__ short srank[Nn];          // bin block only (8 KB)
    __shared__ int   scnt [CELLS];
    __shared__ int   sscan[256];
    __shared__ int   sst  [CELLS+1];     // bin: starts; knn: cached starts

    int tid = threadIdx.x;
    int bid = blockIdx.x;
    int warp = tid >> 5, lane = tid & 31;

    if (bid == 0) {
        // ------------------- BINNING (count + scan + scatter) -------------
        if (tid < CELLS) scnt[tid] = 0;
        __syncthreads();

#pragma unroll
        for (int ii = 0; ii < 16; ii++) {
            int i = tid + 256*ii;
            float4 p = ((const float4*)pos)[i];
            float cx = 0.5f*(p.x+p.z), cy = 0.5f*(p.y+p.w);
            g_c[i] = make_float2(cx, cy);
            int bx = min((int)(cx * INV_CELL), GX-1);
            int by = min((int)(cy * INV_CELL), GY-1);
            srank[i] = (short)atomicAdd(&scnt[by*GX + bx], 1);
        }
        __syncthreads();

        sscan[tid] = (tid < CELLS) ? scnt[tid] : 0;
        __syncthreads();
#pragma unroll
        for (int o = 1; o < 256; o <<= 1) {
            int x = (tid >= o) ? sscan[tid-o] : 0;
            __syncthreads();
            sscan[tid] += x;
            __syncthreads();
        }
        if (tid < CELLS) { sst[tid+1] = sscan[tid]; g_start[tid+1] = sscan[tid]; }
        if (tid == 0)    { sst[0] = 0;              g_start[0] = 0; }
        __syncthreads();

#pragma unroll
        for (int ii = 0; ii < 16; ii++) {
            int i = tid + 256*ii;
            float2 c = g_c[i];
            int bx = min((int)(c.x * INV_CELL), GX-1);
            int by = min((int)(c.y * INV_CELL), GY-1);
            int p = sst[by*GX + bx] + (int)srank[i];
            g_bc4[p] = make_float4(c.x, c.y, __int_as_float(i), 0.0f);
        }
        __syncthreads();
        __threadfence();
        if (tid == 0) atomicExch(&g_flag, 1);
        return;
    }

    int i = (bid - 1) * 8 + warp;        // this warp's node/row

    // ---- FULL norm: read reid once, reduce, write normalized row ----
    // (runs concurrently with binning; no dependency on bin flag)
    {
        const float4* r = (const float4*)(reid + (size_t)i * FD);
        float4 v[4];
        float s = 0.0f;
#pragma unroll
        for (int u = 0; u < 4; u++) {
            v[u] = r[lane + 32*u];
            s += v[u].x*v[u].x + v[u].y*v[u].y + v[u].z*v[u].z + v[u].w*v[u].w;
        }
#pragma unroll
        for (int o = 16; o > 0; o >>= 1) s += __shfl_xor_sync(0xffffffffu, s, o);
        float inv = 1.0f / (sqrtf(s) + 1e-12f);

        float4* o4 = (float4*)(out + (size_t)i * NFW);
#pragma unroll
        for (int u = 0; u < 4; u++) {
            float4 w = v[u];
            w.x *= inv; w.y *= inv; w.z *= inv; w.w *= inv;
            o4[lane + 32*u] = w;
        }
        if (lane == 0) {
            g_inv[i] = inv;
            float4 p = ((const float4*)pos)[i];
            float cx = 0.5f*(p.x+p.z), cy = 0.5f*(p.y+p.w);
            float w = p.z - p.x, h = p.w - p.y;
            float* o = out + (size_t)i * NFW;
            o[512] = cx / 1920.0f;
            o[513] = cy / 1080.0f;
            o[514] = w  / 1920.0f;
            o[515] = h  / 1080.0f;
        }
    }

    // ---- wait for binning ----
    if (tid == 0) {
        while (atomicAdd(&g_flag, 0) == 0) { __nanosleep(64); }
    }
    __syncthreads();
    __threadfence();

    if (tid < CELLS+1) sst[tid] = g_start[tid];
    __syncthreads();

    // ---- KNN over 3x3 cell ring ----
    float2 ci = g_c[i];
    int bx = min((int)(ci.x * INV_CELL), GX-1);
    int by = min((int)(ci.y * INV_CELL), GY-1);

    float dist[KK]; int idx[KK];
#pragma unroll
    for (int u = 0; u < KK; u++) { dist[u] = SENT_D; idx[u] = SENT_I; }

    int y0 = max(by-1, 0), y1 = min(by+1, GY-1);
    int x0 = max(bx-1, 0), x1 = min(bx+1, GX-1);
    for (int cy2 = y0; cy2 <= y1; cy2++) {
        int st = sst[cy2*GX + x0], en = sst[cy2*GX + x1 + 1];
        for (int p = st + lane; p < en; p += 32) {
            float4 b = __ldg(&g_bc4[p]);
            int j = __float_as_int(b.z);
            float dx = ci.x - b.x;
            float dy = ci.y - b.y;
            float d2 = dx*dx + dy*dy;
            if (j != i && d2 <= DIST_T2) {
                float Dv = sqrtf(fmaxf(d2, 1e-12f));
                if (Dv <= DIST_T) {
                    float kd = Dv; int ki = j;
#pragma unroll
                    for (int u = 0; u < KK; u++) {
                        bool sw = (kd < dist[u]) || (kd == dist[u] && ki < idx[u]);
                        if (sw) {
                            float td = dist[u]; int ti = idx[u];
                            dist[u] = kd; idx[u] = ki;
                            kd = td; ki = ti;
                        }
                    }
                }
            }
        }
    }

    // warp merge: 8 rounds of packed (distBits, idx) min-reduce
    float res_d[KK]; int res_i[KK];
#pragma unroll
    for (int k = 0; k < KK; k++) {
        unsigned long long key =
            ((unsigned long long)__float_as_uint(dist[0]) << 32) | (unsigned)idx[0];
#pragma unroll
        for (int o = 16; o > 0; o >>= 1) {
            unsigned long long other = __shfl_xor_sync(0xffffffffu, key, o);
            if (other < key) key = other;
        }
        res_d[k] = __uint_as_float((unsigned)(key >> 32));
        res_i[k] = (int)(unsigned)(key & 0xffffffffull);
        unsigned long long mine =
            ((unsigned long long)__float_as_uint(dist[0]) << 32) | (unsigned)idx[0];
        if (mine == key) {
#pragma unroll
            for (int u = 0; u < KK-1; u++) { dist[u] = dist[u+1]; idx[u] = idx[u+1]; }
            dist[KK-1] = SENT_D; idx[KK-1] = SENT_I;
        }
    }
    // res_* now warp-uniform

    // ---- lanes 0..7: per-edge scalar stash ----
    if (lane < KK) {
        float d = SENT_D; int di = 0;
#pragma unroll
        for (int j = 0; j < KK; j++)
            if (lane == j) { d = res_d[j]; di = res_i[j]; }
        bool val = d < 1e9f;
        int dst = val ? di : 0;
        float m = val ? 1.0f : 0.0f;
        int e = i*KK + lane;

        float4 pi = ((const float4*)pos)[i];
        float4 pd = ((const float4*)pos)[dst];
        float cxi = 0.5f*(pi.x+pi.z), cyi = 0.5f*(pi.y+pi.w);
        float cxd = 0.5f*(pd.x+pd.z), cyd = 0.5f*(pd.y+pd.w);
        float wi = pi.z-pi.x, hi = pi.w-pi.y;
        float wd = pd.z-pd.x, hd = pd.w-pd.y;

        float xd = (cxi - cxd) / 1920.0f;
        float yd = (cyi - cyd) / 1080.0f;
        float ix1 = fmaxf(pi.x, pd.x), iy1 = fmaxf(pi.y, pd.y);
        float ix2 = fminf(pi.z, pd.z), iy2 = fminf(pi.w, pd.w);
        float inter = fmaxf(ix2-ix1, 0.0f) * fmaxf(iy2-iy1, 0.0f);
        float iou = inter / (wi*hi + wd*hd - inter + 1e-12f);
        float lw = logf(wi / wd);
        float lh = logf(hi / hd);

        g_head[e*5+0] = xd  * m;
        g_head[e*5+1] = yd  * m;
        g_head[e*5+2] = iou * m;
        g_head[e*5+3] = lw  * m;
        g_head[e*5+4] = lh  * m;
        g_em[e] = make_float2(m, __int_as_float(dst));

        out[EI_OFF + e]       = (float)i;
        out[EI_OFF + NKE + e] = (float)dst;
        out[MASK_OFF + e]     = m;

        if (lane == 0) {
            float occf = 0.0f;
            if (val) occf = (inter > wi*hi*0.5f) ? 1.0f : 0.0f;
            out[OCC_OFF + i] = occf;
        }
    }

    // ---- lane 0: topology features (nb_dist, angles) ----
    if (lane == 0) {
        bool val[KK]; float nd[KK], vx[KK], vy[KK];
#pragma unroll
        for (int k = 0; k < KK; k++) {
            val[k] = res_d[k] < 1e9f;
            nd[k]  = val[k] ? res_d[k] : 0.0f;
            int nik = val[k] ? res_i[k] : 0;
            float2 cn = g_c[nik];
            vx[k] = cn.x - ci.x;
            vy[k] = cn.y - ci.y;
        }
        float* nf = out + (size_t)i * NFW;
#pragma unroll
        for (int k = 0; k < KK; k++) nf[516 + k] = nd[k] / 1080.0f;

        const float LO = (float)(-1.0 + 1e-6);
        const float HI = (float)( 1.0 - 1e-6);
#pragma unroll
        for (int k = 0; k < KK-1; k++) {
            float a = 0.0f;
            if (val[k+1]) {
                float dot = vx[k]*vx[k+1] + vy[k]*vy[k+1];
                float n1 = sqrtf(vx[k]*vx[k] + vy[k]*vy[k]);
                float n2 = sqrtf(vx[k+1]*vx[k+1] + vy[k+1]*vy[k+1]);
                float cs = dot / (n1*n2 + 1e-12f);
                cs = fminf(fmaxf(cs, LO), HI);
                a = acosf(cs) * 57.29577951308232f;
            }
            nf[524 + k] = a / 360.0f;
        }
        nf[531] = 0.0f;
    }
}

// ===========================================================================
// K2: pure edge copy (8192 blocks, two warps per edge, sourcing raw
//     reid * g_inv). Proven R15 code; g_flag reset for graph replay.
// ===========================================================================
__global__ void __launch_bounds__(256)
k_edge(const float* __restrict__ reid, float* __restrict__ out)
{
    if (blockIdx.x == 0 && threadIdx.x == 0) g_flag = 0;  // reset for replay

    const unsigned FULL = 0xffffffffu;
    int wp = threadIdx.x >> 5, lane = threadIdx.x & 31;
    int e = blockIdx.x * 4 + (wp >> 1);
    int half = wp & 1;                   // 0 = src half, 1 = dst half
    int i = e >> 3;

    float2 md = g_em[e];
    float m  = md.x;
    int  dst = __float_as_int(md.y);

    size_t B = EA_OFF + (size_t)e * EAW;
    int r = (e + 1) & 3;                 // (B+5) mod 4
    int a = (4 - r) & 3;                 // leading scalar count
    float4* ea4 = (float4*)(out + B + 5 + a);

    if (half == 0) {
        float sc = g_inv[i] * m;         // exact: m in {0,1}
        const float4* rs4 = (const float4*)(reid + (size_t)i * FD);
        float4 v[4];
#pragma unroll
        for (int u = 0; u < 4; u++) v[u] = __ldg(rs4 + lane + 32*u);

        if (a == 0) {
#pragma unroll
            for (int u = 0; u < 4; u++) {
                float4 f = v[u];
                f.x *= sc; f.y *= sc; f.z *= sc; f.w *= sc;
                __stcs(ea4 + lane + 32*u, f);
            }
        } else {
            float scd = g_inv[dst] * m;
            float4 e4 = __ldg((const float4*)(reid + (size_t)dst * FD)); // dst quad 0
            e4.x *= scd; e4.y *= scd; e4.z *= scd; e4.w *= scd;
#pragma unroll
            for (int u = 0; u < 4; u++) {
                float4 f = v[u];
                f.x *= sc; f.y *= sc; f.z *= sc; f.w *= sc;
                float4 n;
                n.x = __shfl_sync(FULL, f.x, lane + 1);
                n.y = __shfl_sync(FULL, f.y, lane + 1);
                n.z = __shfl_sync(FULL, f.z, lane + 1);
                n.w = __shfl_sync(FULL, f.w, lane + 1);
                float4 vn = v[(u+1)&3];
                float4 f0;
                f0.x = __shfl_sync(FULL, vn.x, 0) * sc;
                f0.y = __shfl_sync(FULL, vn.y, 0) * sc;
                f0.z = __shfl_sync(FULL, vn.z, 0) * sc;
                f0.w = __shfl_sync(FULL, vn.w, 0) * sc;
                if (u == 3) f0 = e4;
                if (lane == 31) n = f0;

                float4 o;
                if      (a == 1) o = make_float4(f.y, f.z, f.w, n.x);
                else if (a == 2) o = make_float4(f.z, f.w, n.x, n.y);
                else             o = make_float4(f.w, n.x, n.y, n.z);
                __stcs(ea4 + lane + 32*u, o);
            }
        }
        // head: cols 0..4 <- g_head; cols 5..5+a-1 <- src reid[0..a)*inv*m
        if (lane < 5)
            __stcs(out + B + lane, g_head[e*5 + lane]);
        else if (lane < 5 + a)
            __stcs(out + B + lane, __ldg(reid + (size_t)i * FD + (lane - 5)) * sc);
    } else {
        float sc = g_inv[dst] * m;
        const float4* rd4 = (const float4*)(reid + (size_t)dst * FD);
        float4 v[4];
#pragma unroll
        for (int u = 0; u < 4; u++) v[u] = __ldg(rd4 + lane + 32*u);

        if (a == 0) {
#pragma unroll
            for (int u = 0; u < 4; u++) {
                float4 f = v[u];
                f.x *= sc; f.y *= sc; f.z *= sc; f.w *= sc;
                __stcs(ea4 + lane + 32*(u+4), f);
            }
        } else {
#pragma unroll
            for (int u = 0; u < 4; u++) {
                float4 f = v[u];
                f.x *= sc; f.y *= sc; f.z *= sc; f.w *= sc;
                float4 n;
                n.x = __shfl_sync(FULL, f.x, lane + 1);
                n.y = __shfl_sync(FULL, f.y, lane + 1);
                n.z = __shfl_sync(FULL, f.z, lane + 1);
                n.w = __shfl_sync(FULL, f.w, lane + 1);
                float4 vn = v[(u+1)&3];
                float4 f0;
                f0.x = __shfl_sync(FULL, vn.x, 0) * sc;
                f0.y = __shfl_sync(FULL, vn.y, 0) * sc;
                f0.z = __shfl_sync(FULL, vn.z, 0) * sc;
                f0.w = __shfl_sync(FULL, vn.w, 0) * sc;
                if (lane == 31) n = f0;

                float4 o;
                if      (a == 1) o = make_float4(f.y, f.z, f.w, n.x);
                else if (a == 2) o = make_float4(f.z, f.w, n.x, n.y);
                else             o = make_float4(f.w, n.x, n.y, n.z);

                int q = lane + 32*(u+4);
                if (q < 255) __stcs(ea4 + q, o);
            }
            // tail: cols 1025+a..1028 <- dst reid[508+a..512)*inv*m
            int t = 4 - a;
            if (lane < t)
                __stcs(out + B + 1025 + a + lane,
                       __ldg(reid + (size_t)dst * FD + 508 + a + lane) * sc);
        }
    }
}

// ---------------------------------------------------------------------------
extern "C" void kernel_launch(void* const* d_in, const int* in_sizes, int n_in,
                              void* d_out, int out_size)
{
    const float* reid = (const float*)d_in[0];
    const float* pos  = (const float*)d_in[1];
    float* out = (float*)d_out;

    k_knn <<<513, 256>>>(reid, pos, out);
    k_edge<<<NKE/4, 256>>>(reid, out);
}